// round 4
// baseline (speedup 1.0000x reference)
#include <cuda_runtime.h>

#define NN   50000
#define EE   600000
#define FEATD 128
#define NH   8
#define HD   16

// ---------------- scratch (static device globals: allocation-guard safe) ---
__device__ float g_q[NN * FEATD];
__device__ float g_k[NN * FEATD];
__device__ float g_v[NN * FEATD];
__device__ float g_agg[NN * FEATD];
__device__ float g_ex[EE * NH];
__device__ float g_ssum[NN * NH];
__device__ int   g_src[EE];
__device__ int   g_dst[EE];
__device__ int   g_is64;

// ---------------- edge-index dtype detection --------------------------------
// If the buffer is int64 (little-endian, values in [0, 50000)), every odd
// 32-bit word is zero. For int32 data those words are random node ids; the
// probability all 16 probes are zero is ~(2e-5)^16 ~ 0.
__global__ void k_detect(const unsigned* __restrict__ ei) {
    unsigned acc = 0;
#pragma unroll
    for (int i = 0; i < 16; i++) acc |= ei[2 * i + 1];
    g_is64 = (acc == 0) ? 1 : 0;
}

__global__ void k_convert(const void* __restrict__ ei) {
    int e = blockIdx.x * blockDim.x + threadIdx.x;
    if (e >= EE) return;
    if (g_is64) {
        const long long* p = (const long long*)ei;
        g_src[e] = (int)p[e];
        g_dst[e] = (int)p[EE + e];
    } else {
        const int* p = (const int*)ei;
        g_src[e] = p[e];
        g_dst[e] = p[EE + e];
    }
}

// ---------------- zero init -------------------------------------------------
__global__ void k_zero(float* __restrict__ a, int na, float* __restrict__ b, int nb) {
    int stride = gridDim.x * blockDim.x;
    int i0 = blockIdx.x * blockDim.x + threadIdx.x;
    for (int i = i0; i < na; i += stride) a[i] = 0.f;
    for (int i = i0; i < nb; i += stride) b[i] = 0.f;
}

// ---------------- fp32 GEMM: out[n][j] = sum_k X[n][k] * W[j][k] + bias[j] --
// Tile: 64 nodes x 128 cols. 256 threads, each computes 4 nodes x 8 cols.
// Xs padded to 132 floats/row, Ws padded to 129 floats/row (bank-conflict free).
static constexpr int XS_STRIDE = 132;
static constexpr int WS_STRIDE = 129;
static constexpr int GEMM_SMEM = (64 * XS_STRIDE + 128 * WS_STRIDE) * 4;  // 99840 B

__global__ void __launch_bounds__(256, 2)
k_gemm(const float* __restrict__ X, const float* __restrict__ W,
       const float* __restrict__ bias, float* __restrict__ out, int nrows) {
    extern __shared__ float sm[];
    float* Xs = sm;                        // [64][132]
    float* Ws = sm + 64 * XS_STRIDE;       // [128][129]

    const int t = threadIdx.x;
    const int row0 = blockIdx.x * 64;

    // load W (128x128) -> smem, 32-bit coalesced
    for (int f = t; f < 128 * 128; f += 256) {
        int j = f >> 7, kk = f & 127;
        Ws[j * WS_STRIDE + kk] = W[f];
    }
    // load X tile (64x128) -> smem, float4 coalesced, zero-fill OOB rows
    for (int f4 = t; f4 < 64 * 32; f4 += 256) {
        int r = f4 >> 5, c4 = f4 & 31;
        int n = row0 + r;
        float4 vv = (n < nrows) ? ((const float4*)X)[n * 32 + c4]
                                : make_float4(0.f, 0.f, 0.f, 0.f);
        *(float4*)&Xs[r * XS_STRIDE + c4 * 4] = vv;
    }
    __syncthreads();

    const int cg = t & 15;   // col group (fast within warp -> coalesced stores)
    const int ng = t >> 4;   // node group

    float acc[4][8];
#pragma unroll
    for (int i = 0; i < 4; i++)
#pragma unroll
        for (int j = 0; j < 8; j++) acc[i][j] = 0.f;

#pragma unroll 4
    for (int kk = 0; kk < 128; kk++) {
        float xv[4], wv[8];
#pragma unroll
        for (int i = 0; i < 4; i++) xv[i] = Xs[(ng + 16 * i) * XS_STRIDE + kk];
#pragma unroll
        for (int j = 0; j < 8; j++) wv[j] = Ws[(cg + 16 * j) * WS_STRIDE + kk];
#pragma unroll
        for (int i = 0; i < 4; i++)
#pragma unroll
            for (int j = 0; j < 8; j++) acc[i][j] += xv[i] * wv[j];
    }

#pragma unroll
    for (int i = 0; i < 4; i++) {
        int n = row0 + ng + 16 * i;
        if (n < nrows) {
#pragma unroll
            for (int j = 0; j < 8; j++) {
                int col = cg + 16 * j;
                out[n * FEATD + col] = acc[i][j] + bias[col];
            }
        }
    }
}

// ---------------- per-edge scores: ex = exp(q[src].k[dst]/4) per head -------
// One warp per edge; lane covers 4 consecutive features (head = lane/4).
__global__ void k_scores(const float* __restrict__ q, const float* __restrict__ k) {
    int gt = blockIdx.x * blockDim.x + threadIdx.x;
    int e = gt >> 5;
    if (e >= EE) return;
    int lane = threadIdx.x & 31;
    int s = g_src[e], d = g_dst[e];

    float4 qv = ((const float4*)q)[s * 32 + lane];
    float4 kv = ((const float4*)k)[d * 32 + lane];
    float p = qv.x * kv.x + qv.y * kv.y + qv.z * kv.z + qv.w * kv.w;
    p += __shfl_xor_sync(0xffffffffu, p, 1);
    p += __shfl_xor_sync(0xffffffffu, p, 2);   // dot over 16 elems per head

    if ((lane & 3) == 0) {
        int h = lane >> 2;
        float exv = __expf(p * 0.25f);         // 1/sqrt(16)
        g_ex[e * NH + h] = exv;
        atomicAdd(&g_ssum[s * NH + h], exv);
    }
}

// ---------------- aggregation: agg[dst] += (ex/ssum) * v[src] ---------------
__global__ void k_agg(const float* __restrict__ v) {
    int gt = blockIdx.x * blockDim.x + threadIdx.x;
    int e = gt >> 5;
    if (e >= EE) return;
    int lane = threadIdx.x & 31;
    int s = g_src[e], d = g_dst[e];
    int h = lane >> 2;

    float w = g_ex[e * NH + h] / g_ssum[s * NH + h];
    float4 vv = ((const float4*)v)[s * 32 + lane];
    float* dst = &g_agg[d * FEATD + lane * 4];
    asm volatile("red.global.add.v4.f32 [%0], {%1,%2,%3,%4};"
                 :: "l"(dst), "f"(w * vv.x), "f"(w * vv.y),
                    "f"(w * vv.z), "f"(w * vv.w)
                 : "memory");
}

// ---------------- launch -----------------------------------------------------
extern "C" void kernel_launch(void* const* d_in, const int* in_sizes, int n_in,
                              void* d_out, int out_size) {
    const float* X  = (const float*)d_in[0];
    const void*  EI = d_in[1];
    const float* Wq = (const float*)d_in[2];
    const float* bq = (const float*)d_in[3];
    const float* Wk = (const float*)d_in[4];
    const float* bk = (const float*)d_in[5];
    const float* Wv = (const float*)d_in[6];
    const float* bv = (const float*)d_in[7];
    const float* Wo = (const float*)d_in[8];
    const float* bo = (const float*)d_in[9];
    float* out = (float*)d_out;

    float *qp, *kp, *vp, *aggp, *ssp;
    cudaGetSymbolAddress((void**)&qp,   g_q);
    cudaGetSymbolAddress((void**)&kp,   g_k);
    cudaGetSymbolAddress((void**)&vp,   g_v);
    cudaGetSymbolAddress((void**)&aggp, g_agg);
    cudaGetSymbolAddress((void**)&ssp,  g_ssum);

    cudaFuncSetAttribute(k_gemm, cudaFuncAttributeMaxDynamicSharedMemorySize,
                         GEMM_SMEM);

    const int GB = (NN + 63) / 64;                 // 782 GEMM blocks
    const int EB = (EE + 255) / 256;               // convert blocks
    const int WB = (EE * 32 + 255) / 256;          // warp-per-edge blocks

    k_detect<<<1, 1>>>((const unsigned*)EI);
    k_convert<<<EB, 256>>>(EI);
    k_zero<<<4096, 256>>>(ssp, NN * NH, aggp, NN * FEATD);

    k_gemm<<<GB, 256, GEMM_SMEM>>>(X, Wq, bq, qp, NN);
    k_gemm<<<GB, 256, GEMM_SMEM>>>(X, Wk, bk, kp, NN);
    k_gemm<<<GB, 256, GEMM_SMEM>>>(X, Wv, bv, vp, NN);

    k_scores<<<WB, 256>>>(qp, kp);
    k_agg<<<WB, 256>>>(vp);

    k_gemm<<<GB, 256, GEMM_SMEM>>>(aggp, Wo, bo, out, NN);
}

// round 8
// speedup vs baseline: 1.1811x; 1.1811x over previous
#include <cuda_runtime.h>
#include <cuda_bf16.h>

#define NN   50000
#define EE   600000
#define FEATD 128
#define NH   8

// ---------------- scratch (static device globals: allocation-guard safe) ---
__device__ float g_q[NN * FEATD];
__device__ float g_k[NN * FEATD];
__device__ float g_v[NN * FEATD];
__device__ float g_agg[NN * FEATD];
__device__ float g_ex[EE * NH];
__device__ float g_ssum[NN * NH];
__device__ int   g_src[EE];
__device__ int   g_dst[EE];
__device__ int   g_is64;
__device__ __nv_bfloat16 g_x1[NN * FEATD];   // hi split of GEMM A operand
__device__ __nv_bfloat16 g_x2[NN * FEATD];   // lo split
__device__ __nv_bfloat16 g_w1[4 * FEATD * FEATD];
__device__ __nv_bfloat16 g_w2[4 * FEATD * FEATD];

// ============================ PTX helpers (arch-agnostic only!) =============
__device__ __forceinline__ unsigned smem_u32(const void* p) {
    unsigned a;
    asm("{ .reg .u64 t; cvta.to.shared.u64 t, %1; cvt.u32.u64 %0, t; }"
        : "=r"(a) : "l"(p));
    return a;
}

#define LDSM_X4(r, addr) \
    asm volatile("ldmatrix.sync.aligned.m8n8.x4.shared.b16 {%0,%1,%2,%3}, [%4];" \
                 : "=r"((r)[0]), "=r"((r)[1]), "=r"((r)[2]), "=r"((r)[3])        \
                 : "r"(addr))

#define MMA_BF16(d, a, b0, b1)                                                  \
    asm volatile("mma.sync.aligned.m16n8k16.row.col.f32.bf16.bf16.f32 "         \
                 "{%0,%1,%2,%3}, {%4,%5,%6,%7}, {%8,%9}, {%0,%1,%2,%3};"        \
                 : "+f"((d)[0]), "+f"((d)[1]), "+f"((d)[2]), "+f"((d)[3])        \
                 : "r"((a)[0]), "r"((a)[1]), "r"((a)[2]), "r"((a)[3]),           \
                   "r"(b0), "r"(b1))

// ================= bf16 split: s = hi + lo (to ~2^-17 rel) ==================
__global__ void k_split(const float* __restrict__ s, __nv_bfloat16* __restrict__ hi,
                        __nv_bfloat16* __restrict__ lo, int n) {
    int i = blockIdx.x * blockDim.x + threadIdx.x;
    if (i >= n) return;
    float v = s[i];
    __nv_bfloat16 h = __float2bfloat16(v);
    hi[i] = h;
    lo[i] = __float2bfloat16(v - __bfloat162float(h));
}

// =================== mma.sync GEMM: out = A @ W^T + bias ====================
// A: [nrows,128] fp32 via bf16 splits (A1+A2). W: [128,128] via (B1+B2).
// D = A1B1 + A1B2 + A2B1 (fp32 accum). Tile 128x128, 8 warps as 4(M) x 2(N),
// warp tile 32x64 = 2 m16-frags x 8 n8-frags, k-loop 8 x k16.
// Smem rows strided 272 B (17 x 16B banks -> ldmatrix conflict-free).
static constexpr int TSTR  = 136;                   // bf16 per smem row
static constexpr int TBYTES = 128 * TSTR * 2;       // 34816 per tile
static constexpr int SM_X1 = 0;
static constexpr int SM_X2 = TBYTES;
static constexpr int SM_W1 = 2 * TBYTES;
static constexpr int SM_W2 = 3 * TBYTES;
static constexpr int SM_BIAS = 4 * TBYTES;          // 139264
static constexpr int GEMM_SMEM = SM_BIAS + 512;     // 139776 B

__device__ __forceinline__ void tile_to_smem(char* sm, int off,
                                             const __nv_bfloat16* __restrict__ g,
                                             int row0, int nrows) {
    // 128 rows x 128 bf16, 16B chunks: 2048 chunks over 256 threads
    for (int c = threadIdx.x; c < 2048; c += 256) {
        int r = c >> 4, k16 = c & 15;
        uint4 v = make_uint4(0u, 0u, 0u, 0u);
        int gr = row0 + r;
        if (gr < nrows) v = *(const uint4*)(g + (size_t)gr * FEATD + k16 * 8);
        *(uint4*)(sm + off + r * 272 + k16 * 16) = v;
    }
}

__global__ void __launch_bounds__(256, 1)
k_gemm_mma(const __nv_bfloat16* __restrict__ A1, const __nv_bfloat16* __restrict__ A2,
           const __nv_bfloat16* __restrict__ B1, const __nv_bfloat16* __restrict__ B2,
           const float* __restrict__ bias, float* __restrict__ out, int nrows) {
    extern __shared__ char sm[];
    const int tid = threadIdx.x, wid = tid >> 5, lane = tid & 31;
    const int row0 = blockIdx.x * 128;

    if (tid < FEATD) ((float*)(sm + SM_BIAS))[tid] = bias[tid];
    tile_to_smem(sm, SM_W1, B1, 0, 128);
    tile_to_smem(sm, SM_W2, B2, 0, 128);
    tile_to_smem(sm, SM_X1, A1, row0, nrows);
    tile_to_smem(sm, SM_X2, A2, row0, nrows);
    __syncthreads();

    const unsigned sbase = smem_u32(sm);
    const int warp_m = wid & 3, warp_n = wid >> 2;

    // A-fragment lane address: lanes 0-7 rows 0-7 k0, 8-15 rows 8-15 k0,
    // 16-23 rows 0-7 +16B, 24-31 rows 8-15 +16B
    const int a_r    = lane & 15;
    const int a_koff = (lane >> 4) << 4;
    const unsigned a1_base = sbase + SM_X1 + (warp_m * 32 + a_r) * 272 + a_koff;
    const unsigned a2_base = sbase + SM_X2 + (warp_m * 32 + a_r) * 272 + a_koff;

    // B-fragment lane address (W rows are the n dimension):
    // matrices: m0 = n0-7 k0-7, m1 = n0-7 k8-15, m2 = n8-15 k0-7, m3 = n8-15 k8-15
    const int b_r    = (lane & 7) | ((lane & 16) >> 1);
    const int b_koff = (lane & 8) << 1;
    const unsigned b1_base = sbase + SM_W1 + (warp_n * 64 + b_r) * 272 + b_koff;
    const unsigned b2_base = sbase + SM_W2 + (warp_n * 64 + b_r) * 272 + b_koff;

    float acc[2][8][4];
#pragma unroll
    for (int i = 0; i < 2; i++)
#pragma unroll
        for (int j = 0; j < 8; j++)
#pragma unroll
            for (int c = 0; c < 4; c++) acc[i][j][c] = 0.f;

#pragma unroll
    for (int kk = 0; kk < 8; kk++) {
        const unsigned ko = kk * 32;   // 16 bf16 = 32 B per k-step
        unsigned a1[2][4], a2[2][4];
        LDSM_X4(a1[0], a1_base + ko);
        LDSM_X4(a1[1], a1_base + 16 * 272 + ko);
        LDSM_X4(a2[0], a2_base + ko);
        LDSM_X4(a2[1], a2_base + 16 * 272 + ko);

        unsigned b1[4][4], b2[4][4];   // [n16-block][4 regs = two n8 frags]
#pragma unroll
        for (int nb = 0; nb < 4; nb++) {
            LDSM_X4(b1[nb], b1_base + nb * 16 * 272 + ko);
            LDSM_X4(b2[nb], b2_base + nb * 16 * 272 + ko);
        }

#pragma unroll
        for (int fm = 0; fm < 2; fm++)
#pragma unroll
            for (int nb = 0; nb < 4; nb++) {
                MMA_BF16(acc[fm][2 * nb + 0], a1[fm], b1[nb][0], b1[nb][1]);
                MMA_BF16(acc[fm][2 * nb + 1], a1[fm], b1[nb][2], b1[nb][3]);
                MMA_BF16(acc[fm][2 * nb + 0], a1[fm], b2[nb][0], b2[nb][1]);
                MMA_BF16(acc[fm][2 * nb + 1], a1[fm], b2[nb][2], b2[nb][3]);
                MMA_BF16(acc[fm][2 * nb + 0], a2[fm], b1[nb][0], b1[nb][1]);
                MMA_BF16(acc[fm][2 * nb + 1], a2[fm], b1[nb][2], b1[nb][3]);
            }
    }

    // epilogue: C frag lane mapping g = lane>>2 (row), t = lane&3 (col pair)
    const int g = lane >> 2, t = lane & 3;
    const float* bs = (const float*)(sm + SM_BIAS);
#pragma unroll
    for (int fm = 0; fm < 2; fm++) {
        const int r0 = row0 + warp_m * 32 + fm * 16 + g;
#pragma unroll
        for (int fn = 0; fn < 8; fn++) {
            const int col = warp_n * 64 + fn * 8 + 2 * t;
            if (r0 < nrows) {
                float2 o = make_float2(acc[fm][fn][0] + bs[col],
                                       acc[fm][fn][1] + bs[col + 1]);
                *(float2*)(out + (size_t)r0 * FEATD + col) = o;
            }
            if (r0 + 8 < nrows) {
                float2 o = make_float2(acc[fm][fn][2] + bs[col],
                                       acc[fm][fn][3] + bs[col + 1]);
                *(float2*)(out + (size_t)(r0 + 8) * FEATD + col) = o;
            }
        }
    }
}

// ---------------- edge-index dtype detection --------------------------------
__global__ void k_detect(const unsigned* __restrict__ ei) {
    unsigned acc = 0;
#pragma unroll
    for (int i = 0; i < 16; i++) acc |= ei[2 * i + 1];
    g_is64 = (acc == 0) ? 1 : 0;
}

__global__ void k_convert(const void* __restrict__ ei) {
    int e = blockIdx.x * blockDim.x + threadIdx.x;
    if (e >= EE) return;
    if (g_is64) {
        const long long* p = (const long long*)ei;
        g_src[e] = (int)p[e];
        g_dst[e] = (int)p[EE + e];
    } else {
        const int* p = (const int*)ei;
        g_src[e] = p[e];
        g_dst[e] = p[EE + e];
    }
}

__global__ void k_zero(float* __restrict__ a, int na, float* __restrict__ b, int nb) {
    int stride = gridDim.x * blockDim.x;
    int i0 = blockIdx.x * blockDim.x + threadIdx.x;
    for (int i = i0; i < na; i += stride) a[i] = 0.f;
    for (int i = i0; i < nb; i += stride) b[i] = 0.f;
}

// ---------------- per-edge scores: ex = exp(q[src].k[dst]/4) per head -------
__global__ void k_scores(const float* __restrict__ q, const float* __restrict__ k) {
    int gt = blockIdx.x * blockDim.x + threadIdx.x;
    int e = gt >> 5;
    if (e >= EE) return;
    int lane = threadIdx.x & 31;
    int s = g_src[e], d = g_dst[e];

    float4 qv = ((const float4*)q)[s * 32 + lane];
    float4 kv = ((const float4*)k)[d * 32 + lane];
    float p = qv.x * kv.x + qv.y * kv.y + qv.z * kv.z + qv.w * kv.w;
    p += __shfl_xor_sync(0xffffffffu, p, 1);
    p += __shfl_xor_sync(0xffffffffu, p, 2);

    if ((lane & 3) == 0) {
        int h = lane >> 2;
        float exv = __expf(p * 0.25f);
        g_ex[e * NH + h] = exv;
        atomicAdd(&g_ssum[s * NH + h], exv);
    }
}

// ---------------- aggregation: agg[dst] += (ex/ssum) * v[src] ---------------
__global__ void k_agg(const float* __restrict__ v) {
    int gt = blockIdx.x * blockDim.x + threadIdx.x;
    int e = gt >> 5;
    if (e >= EE) return;
    int lane = threadIdx.x & 31;
    int s = g_src[e], d = g_dst[e];
    int h = lane >> 2;

    float w = g_ex[e * NH + h] / g_ssum[s * NH + h];
    float4 vv = ((const float4*)v)[s * 32 + lane];
    float* dst = &g_agg[d * FEATD + lane * 4];
    asm volatile("red.global.add.v4.f32 [%0], {%1,%2,%3,%4};"
                 :: "l"(dst), "f"(w * vv.x), "f"(w * vv.y),
                    "f"(w * vv.z), "f"(w * vv.w)
                 : "memory");
}

// ---------------- launch -----------------------------------------------------
extern "C" void kernel_launch(void* const* d_in, const int* in_sizes, int n_in,
                              void* d_out, int out_size) {
    const float* X  = (const float*)d_in[0];
    const void*  EI = d_in[1];
    const float* Wq = (const float*)d_in[2];
    const float* bq = (const float*)d_in[3];
    const float* Wk = (const float*)d_in[4];
    const float* bk = (const float*)d_in[5];
    const float* Wv = (const float*)d_in[6];
    const float* bv = (const float*)d_in[7];
    const float* Wo = (const float*)d_in[8];
    const float* bo = (const float*)d_in[9];
    float* out = (float*)d_out;

    float *qp, *kp, *vp, *aggp, *ssp;
    __nv_bfloat16 *x1, *x2, *w1, *w2;
    cudaGetSymbolAddress((void**)&qp,   g_q);
    cudaGetSymbolAddress((void**)&kp,   g_k);
    cudaGetSymbolAddress((void**)&vp,   g_v);
    cudaGetSymbolAddress((void**)&aggp, g_agg);
    cudaGetSymbolAddress((void**)&ssp,  g_ssum);
    cudaGetSymbolAddress((void**)&x1,   g_x1);
    cudaGetSymbolAddress((void**)&x2,   g_x2);
    cudaGetSymbolAddress((void**)&w1,   g_w1);
    cudaGetSymbolAddress((void**)&w2,   g_w2);

    cudaFuncSetAttribute(k_gemm_mma, cudaFuncAttributeMaxDynamicSharedMemorySize,
                         GEMM_SMEM);

    const int NF = NN * FEATD;
    const int WE = FEATD * FEATD;
    const int EB = (EE + 255) / 256;
    const int WB = (EE * 32 + 255) / 256;
    const int SB = (NF + 255) / 256;
    const int SW = (WE + 255) / 256;
    const int GB = (NN + 127) / 128;               // 391 GEMM tiles

    k_detect<<<1, 1>>>((const unsigned*)EI);
    k_convert<<<EB, 256>>>(EI);
    k_zero<<<4096, 256>>>(ssp, NN * NH, aggp, NF);

    // splits: X once (shared by Q/K/V GEMMs), weights once each
    k_split<<<SB, 256>>>(X, x1, x2, NF);
    k_split<<<SW, 256>>>(Wq, w1 + 0 * WE, w2 + 0 * WE, WE);
    k_split<<<SW, 256>>>(Wk, w1 + 1 * WE, w2 + 1 * WE, WE);
    k_split<<<SW, 256>>>(Wv, w1 + 2 * WE, w2 + 2 * WE, WE);
    k_split<<<SW, 256>>>(Wo, w1 + 3 * WE, w2 + 3 * WE, WE);

    k_gemm_mma<<<GB, 256, GEMM_SMEM>>>(x1, x2, w1 + 0 * WE, w2 + 0 * WE, bq, qp, NN);
    k_gemm_mma<<<GB, 256, GEMM_SMEM>>>(x1, x2, w1 + 1 * WE, w2 + 1 * WE, bk, kp, NN);
    k_gemm_mma<<<GB, 256, GEMM_SMEM>>>(x1, x2, w1 + 2 * WE, w2 + 2 * WE, bv, vp, NN);

    k_scores<<<WB, 256>>>(qp, kp);
    k_agg<<<WB, 256>>>(vp);

    // output projection: split agg (reuses x1/x2), then GEMM into d_out
    k_split<<<SB, 256>>>(aggp, x1, x2, NF);
    k_gemm_mma<<<GB, 256, GEMM_SMEM>>>(x1, x2, w1 + 3 * WE, w2 + 3 * WE, bo, out, NN);
}

// round 9
// speedup vs baseline: 1.3174x; 1.1153x over previous
#include <cuda_runtime.h>
#include <cuda_bf16.h>

#define NN   50000
#define EE   600000
#define FEATD 128
#define NH   8

// ---------------- scratch (static device globals: allocation-guard safe) ---
__device__ float g_q[NN * FEATD];
__device__ float g_k[NN * FEATD];
__device__ float g_v[NN * FEATD];
__device__ float g_agg[NN * FEATD];
__device__ float g_ex[EE * NH];
__device__ float g_ssum[NN * NH];
__device__ int   g_src[EE];
__device__ int   g_dst[EE];
__device__ int   g_is64;

// ============================ PTX helpers (arch-agnostic only!) =============
__device__ __forceinline__ unsigned smem_u32(const void* p) {
    unsigned a;
    asm("{ .reg .u64 t; cvta.to.shared.u64 t, %1; cvt.u32.u64 %0, t; }"
        : "=r"(a) : "l"(p));
    return a;
}

#define LDSM_X4(r, addr) \
    asm volatile("ldmatrix.sync.aligned.m8n8.x4.shared.b16 {%0,%1,%2,%3}, [%4];" \
                 : "=r"((r)[0]), "=r"((r)[1]), "=r"((r)[2]), "=r"((r)[3])        \
                 : "r"(addr))

#define MMA_BF16(d, a, b0, b1)                                                  \
    asm volatile("mma.sync.aligned.m16n8k16.row.col.f32.bf16.bf16.f32 "         \
                 "{%0,%1,%2,%3}, {%4,%5,%6,%7}, {%8,%9}, {%0,%1,%2,%3};"        \
                 : "+f"((d)[0]), "+f"((d)[1]), "+f"((d)[2]), "+f"((d)[3])        \
                 : "r"((a)[0]), "r"((a)[1]), "r"((a)[2]), "r"((a)[3]),           \
                   "r"(b0), "r"(b1))

// =================== fused-split mma.sync GEMM ==============================
// out_j = A @ W_j^T + b_j for j < nmat (QKV: nmat=3 sharing one A tile).
// A fp32 is split in-register to bf16 hi/lo while staging smem:
// D = A1B1 + A1B2 + A2B1 (fp32 accum), rel err ~2^-17.
// Tile 128x128, 8 warps as 4(M) x 2(N); smem rows strided 272 B
// (17 x 16B banks -> ldmatrix conflict-free).
static constexpr int TBYTES  = 128 * 272;            // 34816 per tile
static constexpr int SM_X1   = 0;
static constexpr int SM_X2   = TBYTES;
static constexpr int SM_W1   = 2 * TBYTES;
static constexpr int SM_W2   = 3 * TBYTES;
static constexpr int SM_BIAS = 4 * TBYTES;           // 3 x 128 floats
static constexpr int GEMM_SMEM = SM_BIAS + 3 * 512;  // 140800 B

__device__ __forceinline__ void load_split_tile(char* sm, int offH, int offL,
                                                const float* __restrict__ g,
                                                int row0, int nrows) {
    // 128 rows x 32 float4 chunks
    for (int c = threadIdx.x; c < 4096; c += 256) {
        int r = c >> 5, c4 = c & 31;
        float4 v = make_float4(0.f, 0.f, 0.f, 0.f);
        int gr = row0 + r;
        if (gr < nrows) v = ((const float4*)(g + (size_t)gr * FEATD))[c4];
        __nv_bfloat162 h01 = __floats2bfloat162_rn(v.x, v.y);
        __nv_bfloat162 h23 = __floats2bfloat162_rn(v.z, v.w);
        float2 f01 = __bfloat1622float2(h01);
        float2 f23 = __bfloat1622float2(h23);
        __nv_bfloat162 l01 = __floats2bfloat162_rn(v.x - f01.x, v.y - f01.y);
        __nv_bfloat162 l23 = __floats2bfloat162_rn(v.z - f23.x, v.w - f23.y);
        unsigned base = r * 272 + c4 * 8;
        *(uint2*)(sm + offH + base) =
            make_uint2(*(unsigned*)&h01, *(unsigned*)&h23);
        *(uint2*)(sm + offL + base) =
            make_uint2(*(unsigned*)&l01, *(unsigned*)&l23);
    }
}

__global__ void __launch_bounds__(256, 1)
k_gemm_fused(const float* __restrict__ A,
             const float* __restrict__ W0, const float* __restrict__ W1,
             const float* __restrict__ W2,
             const float* __restrict__ b0, const float* __restrict__ b1,
             const float* __restrict__ b2,
             float* __restrict__ o0, float* __restrict__ o1,
             float* __restrict__ o2,
             int nmat, int nrows) {
    extern __shared__ char sm[];
    const int tid = threadIdx.x, wid = tid >> 5, lane = tid & 31;
    const int row0 = blockIdx.x * 128;

    const float* Ws[3] = { W0, W1, W2 };
    const float* bp[3] = { b0, b1, b2 };
    float*       os[3] = { o0, o1, o2 };

    // biases
    if (tid < FEATD)
        for (int j = 0; j < nmat; j++)
            ((float*)(sm + SM_BIAS))[j * FEATD + tid] = bp[j][tid];

    load_split_tile(sm, SM_X1, SM_X2, A, row0, nrows);
    load_split_tile(sm, SM_W1, SM_W2, Ws[0], 0, 128);
    __syncthreads();

    const unsigned sbase = smem_u32(sm);
    const int warp_m = wid & 3, warp_n = wid >> 2;

    // A-fragment lane address
    const int a_r    = lane & 15;
    const int a_koff = (lane >> 4) << 4;
    const unsigned a1_base = sbase + SM_X1 + (warp_m * 32 + a_r) * 272 + a_koff;
    const unsigned a2_base = sbase + SM_X2 + (warp_m * 32 + a_r) * 272 + a_koff;

    // B-fragment lane address (W rows = n dimension)
    const int b_r    = (lane & 7) | ((lane & 16) >> 1);
    const int b_koff = (lane & 8) << 1;
    const unsigned b1_base = sbase + SM_W1 + (warp_n * 64 + b_r) * 272 + b_koff;
    const unsigned b2_base = sbase + SM_W2 + (warp_n * 64 + b_r) * 272 + b_koff;

    const int g = lane >> 2, t = lane & 3;

    for (int j = 0; j < nmat; j++) {
        float acc[2][8][4];
#pragma unroll
        for (int i = 0; i < 2; i++)
#pragma unroll
            for (int f = 0; f < 8; f++)
#pragma unroll
                for (int c = 0; c < 4; c++) acc[i][f][c] = 0.f;

#pragma unroll
        for (int kk = 0; kk < 8; kk++) {
            const unsigned ko = kk * 32;
            unsigned a1[2][4], a2[2][4];
            LDSM_X4(a1[0], a1_base + ko);
            LDSM_X4(a1[1], a1_base + 16 * 272 + ko);
            LDSM_X4(a2[0], a2_base + ko);
            LDSM_X4(a2[1], a2_base + 16 * 272 + ko);

            unsigned w1[4][4], w2[4][4];
#pragma unroll
            for (int nb = 0; nb < 4; nb++) {
                LDSM_X4(w1[nb], b1_base + nb * 16 * 272 + ko);
                LDSM_X4(w2[nb], b2_base + nb * 16 * 272 + ko);
            }

#pragma unroll
            for (int fm = 0; fm < 2; fm++)
#pragma unroll
                for (int nb = 0; nb < 4; nb++) {
                    MMA_BF16(acc[fm][2 * nb + 0], a1[fm], w1[nb][0], w1[nb][1]);
                    MMA_BF16(acc[fm][2 * nb + 1], a1[fm], w1[nb][2], w1[nb][3]);
                    MMA_BF16(acc[fm][2 * nb + 0], a1[fm], w2[nb][0], w2[nb][1]);
                    MMA_BF16(acc[fm][2 * nb + 1], a1[fm], w2[nb][2], w2[nb][3]);
                    MMA_BF16(acc[fm][2 * nb + 0], a2[fm], w1[nb][0], w1[nb][1]);
                    MMA_BF16(acc[fm][2 * nb + 1], a2[fm], w1[nb][2], w1[nb][3]);
                }
        }

        // epilogue
        const float* bs = (const float*)(sm + SM_BIAS) + j * FEATD;
        float* outj = os[j];
#pragma unroll
        for (int fm = 0; fm < 2; fm++) {
            const int r0 = row0 + warp_m * 32 + fm * 16 + g;
#pragma unroll
            for (int fn = 0; fn < 8; fn++) {
                const int col = warp_n * 64 + fn * 8 + 2 * t;
                if (r0 < nrows) {
                    float2 o = make_float2(acc[fm][fn][0] + bs[col],
                                           acc[fm][fn][1] + bs[col + 1]);
                    *(float2*)(outj + (size_t)r0 * FEATD + col) = o;
                }
                if (r0 + 8 < nrows) {
                    float2 o = make_float2(acc[fm][fn][2] + bs[col],
                                           acc[fm][fn][3] + bs[col + 1]);
                    *(float2*)(outj + (size_t)(r0 + 8) * FEATD + col) = o;
                }
            }
        }

        if (j + 1 < nmat) {
            __syncthreads();   // everyone done reading W smem
            load_split_tile(sm, SM_W1, SM_W2, Ws[j + 1], 0, 128);
            __syncthreads();
        }
    }
}

// ---------------- edge-index dtype detection --------------------------------
__global__ void k_detect(const unsigned* __restrict__ ei) {
    unsigned acc = 0;
#pragma unroll
    for (int i = 0; i < 16; i++) acc |= ei[2 * i + 1];
    g_is64 = (acc == 0) ? 1 : 0;
}

__global__ void k_convert(const void* __restrict__ ei) {
    int e = blockIdx.x * blockDim.x + threadIdx.x;
    if (e >= EE) return;
    if (g_is64) {
        const long long* p = (const long long*)ei;
        g_src[e] = (int)p[e];
        g_dst[e] = (int)p[EE + e];
    } else {
        const int* p = (const int*)ei;
        g_src[e] = p[e];
        g_dst[e] = p[EE + e];
    }
}

__global__ void k_zero(float4* __restrict__ a, int na4, float4* __restrict__ b, int nb4) {
    int stride = gridDim.x * blockDim.x;
    int i0 = blockIdx.x * blockDim.x + threadIdx.x;
    float4 z = make_float4(0.f, 0.f, 0.f, 0.f);
    for (int i = i0; i < na4; i += stride) a[i] = z;
    for (int i = i0; i < nb4; i += stride) b[i] = z;
}

// ---------------- per-edge scores: ex = exp(q[src].k[dst]/4) per head -------
__global__ void k_scores(const float* __restrict__ q, const float* __restrict__ k) {
    int gt = blockIdx.x * blockDim.x + threadIdx.x;
    int e = gt >> 5;
    if (e >= EE) return;
    int lane = threadIdx.x & 31;
    int s = g_src[e], d = g_dst[e];

    float4 qv = ((const float4*)q)[s * 32 + lane];
    float4 kv = ((const float4*)k)[d * 32 + lane];
    float p = qv.x * kv.x + qv.y * kv.y + qv.z * kv.z + qv.w * kv.w;
    p += __shfl_xor_sync(0xffffffffu, p, 1);
    p += __shfl_xor_sync(0xffffffffu, p, 2);

    if ((lane & 3) == 0) {
        int h = lane >> 2;
        float exv = __expf(p * 0.25f);
        g_ex[e * NH + h] = exv;
        atomicAdd(&g_ssum[s * NH + h], exv);
    }
}

// ---------------- aggregation: agg[dst] += (ex/ssum) * v[src] ---------------
__global__ void k_agg(const float* __restrict__ v) {
    int gt = blockIdx.x * blockDim.x + threadIdx.x;
    int e = gt >> 5;
    if (e >= EE) return;
    int lane = threadIdx.x & 31;
    int s = g_src[e], d = g_dst[e];
    int h = lane >> 2;

    float w = g_ex[e * NH + h] / g_ssum[s * NH + h];
    float4 vv = ((const float4*)v)[s * 32 + lane];
    float* dst = &g_agg[d * FEATD + lane * 4];
    asm volatile("red.global.add.v4.f32 [%0], {%1,%2,%3,%4};"
                 :: "l"(dst), "f"(w * vv.x), "f"(w * vv.y),
                    "f"(w * vv.z), "f"(w * vv.w)
                 : "memory");
}

// ---------------- launch -----------------------------------------------------
extern "C" void kernel_launch(void* const* d_in, const int* in_sizes, int n_in,
                              void* d_out, int out_size) {
    const float* X  = (const float*)d_in[0];
    const void*  EI = d_in[1];
    const float* Wq = (const float*)d_in[2];
    const float* bq = (const float*)d_in[3];
    const float* Wk = (const float*)d_in[4];
    const float* bk = (const float*)d_in[5];
    const float* Wv = (const float*)d_in[6];
    const float* bv = (const float*)d_in[7];
    const float* Wo = (const float*)d_in[8];
    const float* bo = (const float*)d_in[9];
    float* out = (float*)d_out;

    float *qp, *kp, *vp, *aggp, *ssp;
    cudaGetSymbolAddress((void**)&qp,   g_q);
    cudaGetSymbolAddress((void**)&kp,   g_k);
    cudaGetSymbolAddress((void**)&vp,   g_v);
    cudaGetSymbolAddress((void**)&aggp, g_agg);
    cudaGetSymbolAddress((void**)&ssp,  g_ssum);

    cudaFuncSetAttribute(k_gemm_fused, cudaFuncAttributeMaxDynamicSharedMemorySize,
                         GEMM_SMEM);

    const int NF = NN * FEATD;
    const int EB = (EE + 255) / 256;
    const int WB = (EE * 32 + 255) / 256;
    const int GB = (NN + 127) / 128;               // 391 GEMM tiles

    k_detect<<<1, 1>>>((const unsigned*)EI);
    k_convert<<<EB, 256>>>(EI);
    k_zero<<<2048, 256>>>((float4*)ssp, NN * NH / 4, (float4*)aggp, NF / 4);

    k_gemm_fused<<<GB, 256, GEMM_SMEM>>>(X, Wq, Wk, Wv, bq, bk, bv,
                                         qp, kp, vp, 3, NN);
    k_scores<<<WB, 256>>>(qp, kp);
    k_agg<<<WB, 256>>>(vp);
    k_gemm_fused<<<GB, 256, GEMM_SMEM>>>(aggp, Wo, Wo, Wo, bo, bo, bo,
                                         out, out, out, 1, NN);
}

// round 13
// speedup vs baseline: 1.4379x; 1.0915x over previous
#include <cuda_runtime.h>
#include <cuda_bf16.h>

#define NN   50000
#define EE   600000
#define FEATD 128
#define NH   8

// ---------------- scratch (static device globals: allocation-guard safe) ---
__device__ float g_q[NN * FEATD];
__device__ float g_k[NN * FEATD];
__device__ float g_v[NN * FEATD];
__device__ float g_agg[NN * FEATD];
__device__ float g_ex[EE * NH];
__device__ float g_ssum[NN * NH];
__device__ int   g_src[EE];
__device__ int   g_dst[EE];
__device__ int   g_is64;

// ============================ PTX helpers (arch-agnostic only!) =============
__device__ __forceinline__ unsigned smem_u32(const void* p) {
    unsigned a;
    asm("{ .reg .u64 t; cvta.to.shared.u64 t, %1; cvt.u32.u64 %0, t; }"
        : "=r"(a) : "l"(p));
    return a;
}

#define LDSM_X4(r, addr) \
    asm volatile("ldmatrix.sync.aligned.m8n8.x4.shared.b16 {%0,%1,%2,%3}, [%4];" \
                 : "=r"((r)[0]), "=r"((r)[1]), "=r"((r)[2]), "=r"((r)[3])        \
                 : "r"(addr))

#define MMA_BF16(d, a, b0, b1)                                                  \
    asm volatile("mma.sync.aligned.m16n8k16.row.col.f32.bf16.bf16.f32 "         \
                 "{%0,%1,%2,%3}, {%4,%5,%6,%7}, {%8,%9}, {%0,%1,%2,%3};"        \
                 : "+f"((d)[0]), "+f"((d)[1]), "+f"((d)[2]), "+f"((d)[3])        \
                 : "r"((a)[0]), "r"((a)[1]), "r"((a)[2]), "r"((a)[3]),           \
                   "r"(b0), "r"(b1))

// =================== fused-split mma.sync GEMM ==============================
// out = A @ W^T + b ; W selected by blockIdx.y. A fp32 split in-register to
// bf16 hi/lo while staging smem: D = A1B1 + A1B2 + A2B1 (rel err ~2^-17).
// Tile 64(M) x 128(N), 8 warps as 2(M) x 4(N), warp tile 32x32.
// Smem rows strided 272 B (17 x 16B banks -> ldmatrix conflict-free).
// 105 KB smem -> 2 CTAs/SM (occ 25%).
static constexpr int SM_X1   = 0;                    // 64 x 272
static constexpr int SM_X2   = 64 * 272;             // 17408
static constexpr int SM_W1   = 2 * 64 * 272;         // 34816, 128 x 272
static constexpr int SM_W2   = SM_W1 + 128 * 272;    // 69632
static constexpr int SM_BIAS = SM_W2 + 128 * 272;    // 104448
static constexpr int GEMM_SMEM = SM_BIAS + 512;      // 104960 B

__device__ __forceinline__ void load_split_tile(char* sm, int offH, int offL,
                                                const float* __restrict__ g,
                                                int row0, int tile_rows, int nrows) {
    for (int c = threadIdx.x; c < tile_rows * 32; c += 256) {
        int r = c >> 5, c4 = c & 31;
        float4 v = make_float4(0.f, 0.f, 0.f, 0.f);
        int gr = row0 + r;
        if (gr < nrows) v = ((const float4*)(g + (size_t)gr * FEATD))[c4];
        __nv_bfloat162 h01 = __floats2bfloat162_rn(v.x, v.y);
        __nv_bfloat162 h23 = __floats2bfloat162_rn(v.z, v.w);
        float2 f01 = __bfloat1622float2(h01);
        float2 f23 = __bfloat1622float2(h23);
        __nv_bfloat162 l01 = __floats2bfloat162_rn(v.x - f01.x, v.y - f01.y);
        __nv_bfloat162 l23 = __floats2bfloat162_rn(v.z - f23.x, v.w - f23.y);
        unsigned base = r * 272 + c4 * 8;
        *(uint2*)(sm + offH + base) =
            make_uint2(*(unsigned*)&h01, *(unsigned*)&h23);
        *(uint2*)(sm + offL + base) =
            make_uint2(*(unsigned*)&l01, *(unsigned*)&l23);
    }
}

__global__ void __launch_bounds__(256, 2)
k_gemm_mma(const float* __restrict__ A,
           const float* __restrict__ W0, const float* __restrict__ W1,
           const float* __restrict__ W2,
           const float* __restrict__ b0, const float* __restrict__ b1,
           const float* __restrict__ b2,
           float* __restrict__ o0, float* __restrict__ o1,
           float* __restrict__ o2, int nrows) {
    extern __shared__ char sm[];
    const int tid = threadIdx.x, wid = tid >> 5, lane = tid & 31;
    const int row0 = blockIdx.x * 64;
    const int j = blockIdx.y;

    const float* W  = (j == 0) ? W0 : (j == 1) ? W1 : W2;
    const float* bp = (j == 0) ? b0 : (j == 1) ? b1 : b2;
    float*      out = (j == 0) ? o0 : (j == 1) ? o1 : o2;

    if (tid < FEATD) ((float*)(sm + SM_BIAS))[tid] = bp[tid];
    load_split_tile(sm, SM_X1, SM_X2, A, row0, 64, nrows);
    load_split_tile(sm, SM_W1, SM_W2, W, 0, 128, 128);
    __syncthreads();

    const unsigned sbase = smem_u32(sm);
    const int warp_m = wid & 1, warp_n = wid >> 1;

    // A-fragment lane address: rows = m dim
    const int a_r    = lane & 15;
    const int a_koff = (lane >> 4) << 4;
    const unsigned a1_base = sbase + SM_X1 + (warp_m * 32 + a_r) * 272 + a_koff;
    const unsigned a2_base = sbase + SM_X2 + (warp_m * 32 + a_r) * 272 + a_koff;

    // B-fragment lane address: W rows = n dim
    const int b_r    = (lane & 7) | ((lane & 16) >> 1);
    const int b_koff = (lane & 8) << 1;
    const unsigned b1_base = sbase + SM_W1 + (warp_n * 32 + b_r) * 272 + b_koff;
    const unsigned b2_base = sbase + SM_W2 + (warp_n * 32 + b_r) * 272 + b_koff;

    float acc[2][4][4];   // [m16 frag][n8 frag][regs]
#pragma unroll
    for (int i = 0; i < 2; i++)
#pragma unroll
        for (int f = 0; f < 4; f++)
#pragma unroll
            for (int c = 0; c < 4; c++) acc[i][f][c] = 0.f;

#pragma unroll
    for (int kk = 0; kk < 8; kk++) {
        const unsigned ko = kk * 32;
        unsigned a1[2][4], a2[2][4];
        LDSM_X4(a1[0], a1_base + ko);
        LDSM_X4(a1[1], a1_base + 16 * 272 + ko);
        LDSM_X4(a2[0], a2_base + ko);
        LDSM_X4(a2[1], a2_base + 16 * 272 + ko);

        unsigned w1[2][4], w2[2][4];   // [n16 block][two n8 frags]
        LDSM_X4(w1[0], b1_base + ko);
        LDSM_X4(w1[1], b1_base + 16 * 272 + ko);
        LDSM_X4(w2[0], b2_base + ko);
        LDSM_X4(w2[1], b2_base + 16 * 272 + ko);

        // term-major order: same acc reused only every 8 MMAs (no RAW stall)
#pragma unroll
        for (int fm = 0; fm < 2; fm++)
#pragma unroll
            for (int nb = 0; nb < 2; nb++) {
                MMA_BF16(acc[fm][2 * nb + 0], a1[fm], w1[nb][0], w1[nb][1]);
                MMA_BF16(acc[fm][2 * nb + 1], a1[fm], w1[nb][2], w1[nb][3]);
            }
#pragma unroll
        for (int fm = 0; fm < 2; fm++)
#pragma unroll
            for (int nb = 0; nb < 2; nb++) {
                MMA_BF16(acc[fm][2 * nb + 0], a1[fm], w2[nb][0], w2[nb][1]);
                MMA_BF16(acc[fm][2 * nb + 1], a1[fm], w2[nb][2], w2[nb][3]);
            }
#pragma unroll
        for (int fm = 0; fm < 2; fm++)
#pragma unroll
            for (int nb = 0; nb < 2; nb++) {
                MMA_BF16(acc[fm][2 * nb + 0], a2[fm], w1[nb][0], w1[nb][1]);
                MMA_BF16(acc[fm][2 * nb + 1], a2[fm], w1[nb][2], w1[nb][3]);
            }
    }

    // epilogue: C frag mapping g = lane>>2 (row), t = lane&3 (col pair)
    const int g = lane >> 2, t = lane & 3;
    const float* bs = (const float*)(sm + SM_BIAS);
#pragma unroll
    for (int fm = 0; fm < 2; fm++) {
        const int r0 = row0 + warp_m * 32 + fm * 16 + g;
#pragma unroll
        for (int fn = 0; fn < 4; fn++) {
            const int col = warp_n * 32 + fn * 8 + 2 * t;
            if (r0 < nrows) {
                float2 o = make_float2(acc[fm][fn][0] + bs[col],
                                       acc[fm][fn][1] + bs[col + 1]);
                *(float2*)(out + (size_t)r0 * FEATD + col) = o;
            }
            if (r0 + 8 < nrows) {
                float2 o = make_float2(acc[fm][fn][2] + bs[col],
                                       acc[fm][fn][3] + bs[col + 1]);
                *(float2*)(out + (size_t)(r0 + 8) * FEATD + col) = o;
            }
        }
    }
}

// ---------------- edge-index dtype detection --------------------------------
__global__ void k_detect(const unsigned* __restrict__ ei) {
    unsigned acc = 0;
#pragma unroll
    for (int i = 0; i < 16; i++) acc |= ei[2 * i + 1];
    g_is64 = (acc == 0) ? 1 : 0;
}

__global__ void k_convert(const void* __restrict__ ei) {
    int e = blockIdx.x * blockDim.x + threadIdx.x;
    if (e >= EE) return;
    if (g_is64) {
        const long long* p = (const long long*)ei;
        g_src[e] = (int)p[e];
        g_dst[e] = (int)p[EE + e];
    } else {
        const int* p = (const int*)ei;
        g_src[e] = p[e];
        g_dst[e] = p[EE + e];
    }
}

__global__ void k_zero(float4* __restrict__ a, int na4, float4* __restrict__ b, int nb4) {
    int stride = gridDim.x * blockDim.x;
    int i0 = blockIdx.x * blockDim.x + threadIdx.x;
    float4 z = make_float4(0.f, 0.f, 0.f, 0.f);
    for (int i = i0; i < na4; i += stride) a[i] = z;
    for (int i = i0; i < nb4; i += stride) b[i] = z;
}

// ---------------- per-edge scores: ex = exp(q[src].k[dst]/4) per head -------
__global__ void k_scores(const float* __restrict__ q, const float* __restrict__ k) {
    int gt = blockIdx.x * blockDim.x + threadIdx.x;
    int e = gt >> 5;
    if (e >= EE) return;
    int lane = threadIdx.x & 31;
    int s = g_src[e], d = g_dst[e];

    float4 qv = ((const float4*)q)[s * 32 + lane];
    float4 kv = ((const float4*)k)[d * 32 + lane];
    float p = qv.x * kv.x + qv.y * kv.y + qv.z * kv.z + qv.w * kv.w;
    p += __shfl_xor_sync(0xffffffffu, p, 1);
    p += __shfl_xor_sync(0xffffffffu, p, 2);

    if ((lane & 3) == 0) {
        int h = lane >> 2;
        float exv = __expf(p * 0.25f);
        g_ex[e * NH + h] = exv;
        atomicAdd(&g_ssum[s * NH + h], exv);
    }
}

// ---------------- aggregation: agg[dst] += (ex/ssum) * v[src] ---------------
__global__ void k_agg(const float* __restrict__ v) {
    int gt = blockIdx.x * blockDim.x + threadIdx.x;
    int e = gt >> 5;
    if (e >= EE) return;
    int lane = threadIdx.x & 31;
    int s = g_src[e], d = g_dst[e];
    int h = lane >> 2;

    float w = g_ex[e * NH + h] / g_ssum[s * NH + h];
    float4 vv = ((const float4*)v)[s * 32 + lane];
    float* dst = &g_agg[d * FEATD + lane * 4];
    asm volatile("red.global.add.v4.f32 [%0], {%1,%2,%3,%4};"
                 :: "l"(dst), "f"(w * vv.x), "f"(w * vv.y),
                    "f"(w * vv.z), "f"(w * vv.w)
                 : "memory");
}

// ---------------- launch -----------------------------------------------------
extern "C" void kernel_launch(void* const* d_in, const int* in_sizes, int n_in,
                              void* d_out, int out_size) {
    const float* X  = (const float*)d_in[0];
    const void*  EI = d_in[1];
    const float* Wq = (const float*)d_in[2];
    const float* bq = (const float*)d_in[3];
    const float* Wk = (const float*)d_in[4];
    const float* bk = (const float*)d_in[5];
    const float* Wv = (const float*)d_in[6];
    const float* bv = (const float*)d_in[7];
    const float* Wo = (const float*)d_in[8];
    const float* bo = (const float*)d_in[9];
    float* out = (float*)d_out;

    float *qp, *kp, *vp, *aggp, *ssp;
    cudaGetSymbolAddress((void**)&qp,   g_q);
    cudaGetSymbolAddress((void**)&kp,   g_k);
    cudaGetSymbolAddress((void**)&vp,   g_v);
    cudaGetSymbolAddress((void**)&aggp, g_agg);
    cudaGetSymbolAddress((void**)&ssp,  g_ssum);

    cudaFuncSetAttribute(k_gemm_mma, cudaFuncAttributeMaxDynamicSharedMemorySize,
                         GEMM_SMEM);

    const int NF = NN * FEATD;
    const int EB = (EE + 255) / 256;
    const int WB = (EE * 32 + 255) / 256;
    const int GB = (NN + 63) / 64;                 // 782 tiles

    k_detect<<<1, 1>>>((const unsigned*)EI);
    k_convert<<<EB, 256>>>(EI);
    k_zero<<<2048, 256>>>((float4*)ssp, NN * NH / 4, (float4*)aggp, NF / 4);

    k_gemm_mma<<<dim3(GB, 3), 256, GEMM_SMEM>>>(X, Wq, Wk, Wv, bq, bk, bv,
                                                qp, kp, vp, NN);
    k_scores<<<WB, 256>>>(qp, kp);
    k_agg<<<WB, 256>>>(vp);
    k_gemm_mma<<<dim3(GB, 1), 256, GEMM_SMEM>>>(aggp, Wo, Wo, Wo, bo, bo, bo,
                                                out, out, out, NN);
}

// round 14
// speedup vs baseline: 1.7190x; 1.1955x over previous
#include <cuda_runtime.h>
#include <cuda_bf16.h>

#define NN   50000
#define EE   600000
#define FEATD 128
#define NH   8

// ---------------- scratch (static device globals: allocation-guard safe) ---
__device__ float g_q[NN * FEATD];
__device__ float g_k[NN * FEATD];
__device__ float g_v[NN * FEATD];
__device__ float g_agg[NN * FEATD];
__device__ float g_ex[EE * NH];          // exp scores -> normalized weights
__device__ int   g_src[EE];
__device__ int   g_dst[EE];
__device__ int   g_is64;
// CSR (both directions)
__device__ int g_deg_s[NN], g_deg_d[NN];
__device__ int g_off_s[NN + 1], g_off_d[NN + 1];
__device__ int g_cur_s[NN], g_cur_d[NN];
__device__ int g_csr_s_dst[EE], g_csr_s_eid[EE];   // by-src: (dst, edge id)
__device__ int g_csr_d_src[EE], g_csr_d_eid[EE];   // by-dst: (src, edge id)

// ============================ PTX helpers (arch-agnostic only!) =============
__device__ __forceinline__ unsigned smem_u32(const void* p) {
    unsigned a;
    asm("{ .reg .u64 t; cvta.to.shared.u64 t, %1; cvt.u32.u64 %0, t; }"
        : "=r"(a) : "l"(p));
    return a;
}

#define LDSM_X4(r, addr) \
    asm volatile("ldmatrix.sync.aligned.m8n8.x4.shared.b16 {%0,%1,%2,%3}, [%4];" \
                 : "=r"((r)[0]), "=r"((r)[1]), "=r"((r)[2]), "=r"((r)[3])        \
                 : "r"(addr))

#define MMA_BF16(d, a, b0, b1)                                                  \
    asm volatile("mma.sync.aligned.m16n8k16.row.col.f32.bf16.bf16.f32 "         \
                 "{%0,%1,%2,%3}, {%4,%5,%6,%7}, {%8,%9}, {%0,%1,%2,%3};"        \
                 : "+f"((d)[0]), "+f"((d)[1]), "+f"((d)[2]), "+f"((d)[3])        \
                 : "r"((a)[0]), "r"((a)[1]), "r"((a)[2]), "r"((a)[3]),           \
                   "r"(b0), "r"(b1))

// =================== fused-split mma.sync GEMM (persistent) =================
// out = A @ W^T + b ; W selected by blockIdx.y, loaded ONCE per block; block
// grid-strides over 64-row A tiles. A fp32 split in-register to bf16 hi/lo:
// D = A1B1 + A1B2 + A2B1 (rel err ~2^-17). 8 warps as 2(M) x 4(N).
// Smem rows strided 272 B (17 x 16B banks -> ldmatrix conflict-free).
static constexpr int SM_X1   = 0;                    // 64 x 272
static constexpr int SM_X2   = 64 * 272;             // 17408
static constexpr int SM_W1   = 2 * 64 * 272;         // 34816, 128 x 272
static constexpr int SM_W2   = SM_W1 + 128 * 272;    // 69632
static constexpr int SM_BIAS = SM_W2 + 128 * 272;    // 104448
static constexpr int GEMM_SMEM = SM_BIAS + 512;      // 104960 B -> 2 CTA/SM

__device__ __forceinline__ void load_split_tile(char* sm, int offH, int offL,
                                                const float* __restrict__ g,
                                                int row0, int tile_rows, int nrows) {
    for (int c = threadIdx.x; c < tile_rows * 32; c += 256) {
        int r = c >> 5, c4 = c & 31;
        float4 v = make_float4(0.f, 0.f, 0.f, 0.f);
        int gr = row0 + r;
        if (gr < nrows) v = ((const float4*)(g + (size_t)gr * FEATD))[c4];
        __nv_bfloat162 h01 = __floats2bfloat162_rn(v.x, v.y);
        __nv_bfloat162 h23 = __floats2bfloat162_rn(v.z, v.w);
        float2 f01 = __bfloat1622float2(h01);
        float2 f23 = __bfloat1622float2(h23);
        __nv_bfloat162 l01 = __floats2bfloat162_rn(v.x - f01.x, v.y - f01.y);
        __nv_bfloat162 l23 = __floats2bfloat162_rn(v.z - f23.x, v.w - f23.y);
        unsigned base = r * 272 + c4 * 8;
        *(uint2*)(sm + offH + base) =
            make_uint2(*(unsigned*)&h01, *(unsigned*)&h23);
        *(uint2*)(sm + offL + base) =
            make_uint2(*(unsigned*)&l01, *(unsigned*)&l23);
    }
}

__global__ void __launch_bounds__(256, 2)
k_gemm_mma(const float* __restrict__ A,
           const float* __restrict__ W0, const float* __restrict__ W1,
           const float* __restrict__ W2,
           const float* __restrict__ b0, const float* __restrict__ b1,
           const float* __restrict__ b2,
           float* __restrict__ o0, float* __restrict__ o1,
           float* __restrict__ o2, int nrows) {
    extern __shared__ char sm[];
    const int tid = threadIdx.x, wid = tid >> 5, lane = tid & 31;
    const int j = blockIdx.y;

    const float* W  = (j == 0) ? W0 : (j == 1) ? W1 : W2;
    const float* bp = (j == 0) ? b0 : (j == 1) ? b1 : b2;
    float*      out = (j == 0) ? o0 : (j == 1) ? o1 : o2;

    if (tid < FEATD) ((float*)(sm + SM_BIAS))[tid] = bp[tid];
    load_split_tile(sm, SM_W1, SM_W2, W, 0, 128, 128);   // once per block

    const unsigned sbase = smem_u32(sm);
    const int warp_m = wid & 1, warp_n = wid >> 1;

    const int a_r    = lane & 15;
    const int a_koff = (lane >> 4) << 4;
    const unsigned a1_base = sbase + SM_X1 + (warp_m * 32 + a_r) * 272 + a_koff;
    const unsigned a2_base = sbase + SM_X2 + (warp_m * 32 + a_r) * 272 + a_koff;

    const int b_r    = (lane & 7) | ((lane & 16) >> 1);
    const int b_koff = (lane & 8) << 1;
    const unsigned b1_base = sbase + SM_W1 + (warp_n * 32 + b_r) * 272 + b_koff;
    const unsigned b2_base = sbase + SM_W2 + (warp_n * 32 + b_r) * 272 + b_koff;

    const int g = lane >> 2, t = lane & 3;
    const float* bs = (const float*)(sm + SM_BIAS);
    const int ntiles = (nrows + 63) >> 6;

    for (int tile = blockIdx.x; tile < ntiles; tile += gridDim.x) {
        const int row0 = tile * 64;
        __syncthreads();   // W ready (1st iter) / prev tile's reads done
        load_split_tile(sm, SM_X1, SM_X2, A, row0, 64, nrows);
        __syncthreads();

        float acc[2][4][4];
#pragma unroll
        for (int i = 0; i < 2; i++)
#pragma unroll
            for (int f = 0; f < 4; f++)
#pragma unroll
                for (int c = 0; c < 4; c++) acc[i][f][c] = 0.f;

#pragma unroll
        for (int kk = 0; kk < 8; kk++) {
            const unsigned ko = kk * 32;
            unsigned a1[2][4], a2[2][4];
            LDSM_X4(a1[0], a1_base + ko);
            LDSM_X4(a1[1], a1_base + 16 * 272 + ko);
            LDSM_X4(a2[0], a2_base + ko);
            LDSM_X4(a2[1], a2_base + 16 * 272 + ko);

            unsigned w1[2][4], w2[2][4];
            LDSM_X4(w1[0], b1_base + ko);
            LDSM_X4(w1[1], b1_base + 16 * 272 + ko);
            LDSM_X4(w2[0], b2_base + ko);
            LDSM_X4(w2[1], b2_base + 16 * 272 + ko);

            // term-major: same acc reused only every 8 MMAs (no RAW stall)
#pragma unroll
            for (int fm = 0; fm < 2; fm++)
#pragma unroll
                for (int nb = 0; nb < 2; nb++) {
                    MMA_BF16(acc[fm][2 * nb + 0], a1[fm], w1[nb][0], w1[nb][1]);
                    MMA_BF16(acc[fm][2 * nb + 1], a1[fm], w1[nb][2], w1[nb][3]);
                }
#pragma unroll
            for (int fm = 0; fm < 2; fm++)
#pragma unroll
                for (int nb = 0; nb < 2; nb++) {
                    MMA_BF16(acc[fm][2 * nb + 0], a1[fm], w2[nb][0], w2[nb][1]);
                    MMA_BF16(acc[fm][2 * nb + 1], a1[fm], w2[nb][2], w2[nb][3]);
                }
#pragma unroll
            for (int fm = 0; fm < 2; fm++)
#pragma unroll
                for (int nb = 0; nb < 2; nb++) {
                    MMA_BF16(acc[fm][2 * nb + 0], a2[fm], w1[nb][0], w1[nb][1]);
                    MMA_BF16(acc[fm][2 * nb + 1], a2[fm], w1[nb][2], w1[nb][3]);
                }
        }

#pragma unroll
        for (int fm = 0; fm < 2; fm++) {
            const int r0 = row0 + warp_m * 32 + fm * 16 + g;
#pragma unroll
            for (int fn = 0; fn < 4; fn++) {
                const int col = warp_n * 32 + fn * 8 + 2 * t;
                if (r0 < nrows) {
                    float2 o = make_float2(acc[fm][fn][0] + bs[col],
                                           acc[fm][fn][1] + bs[col + 1]);
                    *(float2*)(out + (size_t)r0 * FEATD + col) = o;
                }
                if (r0 + 8 < nrows) {
                    float2 o = make_float2(acc[fm][fn][2] + bs[col],
                                           acc[fm][fn][3] + bs[col + 1]);
                    *(float2*)(out + (size_t)(r0 + 8) * FEATD + col) = o;
                }
            }
        }
    }
}

// ---------------- edge-index dtype detection --------------------------------
__global__ void k_detect(const unsigned* __restrict__ ei) {
    unsigned acc = 0;
#pragma unroll
    for (int i = 0; i < 16; i++) acc |= ei[2 * i + 1];
    g_is64 = (acc == 0) ? 1 : 0;
}

__global__ void k_zero_deg() {
    int i = blockIdx.x * blockDim.x + threadIdx.x;
    if (i < NN) { g_deg_s[i] = 0; g_deg_d[i] = 0; }
}

// convert + degree histogram
__global__ void k_convert(const void* __restrict__ ei) {
    int e = blockIdx.x * blockDim.x + threadIdx.x;
    if (e >= EE) return;
    int s, d;
    if (g_is64) {
        const long long* p = (const long long*)ei;
        s = (int)p[e]; d = (int)p[EE + e];
    } else {
        const int* p = (const int*)ei;
        s = p[e]; d = p[EE + e];
    }
    g_src[e] = s; g_dst[e] = d;
    atomicAdd(&g_deg_s[s], 1);
    atomicAdd(&g_deg_d[d], 1);
}

// single-block exclusive scan of both degree arrays (shfl-based)
__global__ void __launch_bounds__(1024, 1) k_scan() {
    __shared__ int wsum_s[32], wsum_d[32], woff_s[32], woff_d[32];
    __shared__ int run[2];
    const int tid = threadIdx.x, lane = tid & 31, wid = tid >> 5;
    if (tid == 0) { run[0] = 0; run[1] = 0; }
    __syncthreads();

    for (int base = 0; base < NN; base += 1024) {
        int i = base + tid;
        int vs = (i < NN) ? g_deg_s[i] : 0;
        int vd = (i < NN) ? g_deg_d[i] : 0;
        int ss = vs, sd = vd;
#pragma unroll
        for (int o = 1; o < 32; o <<= 1) {
            int ts = __shfl_up_sync(0xffffffffu, ss, o);
            int td = __shfl_up_sync(0xffffffffu, sd, o);
            if (lane >= o) { ss += ts; sd += td; }
        }
        if (lane == 31) { wsum_s[wid] = ss; wsum_d[wid] = sd; }
        __syncthreads();
        if (wid == 0) {
            int xs = wsum_s[lane], xd = wsum_d[lane];
            int is = xs, id = xd;
#pragma unroll
            for (int o = 1; o < 32; o <<= 1) {
                int ts = __shfl_up_sync(0xffffffffu, is, o);
                int td = __shfl_up_sync(0xffffffffu, id, o);
                if (lane >= o) { is += ts; id += td; }
            }
            woff_s[lane] = is - xs;   // exclusive
            woff_d[lane] = id - xd;
        }
        __syncthreads();
        int incl_s = ss + woff_s[wid];
        int incl_d = sd + woff_d[wid];
        if (i < NN) {
            int es = run[0] + incl_s - vs;
            int ed = run[1] + incl_d - vd;
            g_off_s[i] = es; g_cur_s[i] = es;
            g_off_d[i] = ed; g_cur_d[i] = ed;
        }
        __syncthreads();
        if (tid == 1023) { run[0] += incl_s; run[1] += incl_d; }
        __syncthreads();
    }
    if (threadIdx.x == 0) { g_off_s[NN] = run[0]; g_off_d[NN] = run[1]; }
}

__global__ void k_scatter() {
    int e = blockIdx.x * blockDim.x + threadIdx.x;
    if (e >= EE) return;
    int s = g_src[e], d = g_dst[e];
    int ps = atomicAdd(&g_cur_s[s], 1);
    g_csr_s_dst[ps] = d; g_csr_s_eid[ps] = e;
    int pd = atomicAdd(&g_cur_d[d], 1);
    g_csr_d_src[pd] = s; g_csr_d_eid[pd] = e;
}

// ------- scores (warp per src node): softmax over outgoing edges, no atomics
__global__ void k_scores_csr(const float* __restrict__ q,
                             const float* __restrict__ k) {
    int n = (blockIdx.x * blockDim.x + threadIdx.x) >> 5;
    if (n >= NN) return;
    int lane = threadIdx.x & 31;
    float4 qv = ((const float4*)q)[n * 32 + lane];   // q held in registers
    int beg = g_off_s[n], end = g_off_s[n + 1];

    float ssum = 0.f;   // per-head sum lives in lanes with (lane&3)==0
    for (int j = beg; j < end; j++) {
        int d = g_csr_s_dst[j];
        int e = g_csr_s_eid[j];
        float4 kv = ((const float4*)k)[d * 32 + lane];
        float p = qv.x * kv.x + qv.y * kv.y + qv.z * kv.z + qv.w * kv.w;
        p += __shfl_xor_sync(0xffffffffu, p, 1);
        p += __shfl_xor_sync(0xffffffffu, p, 2);
        if ((lane & 3) == 0) {
            float exv = __expf(p * 0.25f);
            g_ex[e * NH + (lane >> 2)] = exv;
            ssum += exv;
        }
    }
    // normalize in place: g_ex becomes final weights
    if ((lane & 3) == 0 && end > beg) {
        float inv = 1.f / ssum;
        int h = lane >> 2;
        for (int j = beg; j < end; j++) {
            int e = g_csr_s_eid[j];
            g_ex[e * NH + h] *= inv;
        }
    }
}

// ------- aggregation (warp per dst node): register accumulate, single store
__global__ void k_agg_csr(const float* __restrict__ v, float* __restrict__ agg) {
    int n = (blockIdx.x * blockDim.x + threadIdx.x) >> 5;
    if (n >= NN) return;
    int lane = threadIdx.x & 31;
    int h = lane >> 2;
    int beg = g_off_d[n], end = g_off_d[n + 1];

    float4 acc = make_float4(0.f, 0.f, 0.f, 0.f);
    for (int j = beg; j < end; j++) {
        int s = g_csr_d_src[j];
        int e = g_csr_d_eid[j];
        float w = g_ex[e * NH + h];
        float4 vv = ((const float4*)v)[s * 32 + lane];
        acc.x += w * vv.x; acc.y += w * vv.y;
        acc.z += w * vv.z; acc.w += w * vv.w;
    }
    ((float4*)agg)[n * 32 + lane] = acc;
}

// ---------------- launch -----------------------------------------------------
extern "C" void kernel_launch(void* const* d_in, const int* in_sizes, int n_in,
                              void* d_out, int out_size) {
    const float* X  = (const float*)d_in[0];
    const void*  EI = d_in[1];
    const float* Wq = (const float*)d_in[2];
    const float* bq = (const float*)d_in[3];
    const float* Wk = (const float*)d_in[4];
    const float* bk = (const float*)d_in[5];
    const float* Wv = (const float*)d_in[6];
    const float* bv = (const float*)d_in[7];
    const float* Wo = (const float*)d_in[8];
    const float* bo = (const float*)d_in[9];
    float* out = (float*)d_out;

    float *qp, *kp, *vp, *aggp;
    cudaGetSymbolAddress((void**)&qp,   g_q);
    cudaGetSymbolAddress((void**)&kp,   g_k);
    cudaGetSymbolAddress((void**)&vp,   g_v);
    cudaGetSymbolAddress((void**)&aggp, g_agg);

    cudaFuncSetAttribute(k_gemm_mma, cudaFuncAttributeMaxDynamicSharedMemorySize,
                         GEMM_SMEM);

    const int EB = (EE + 255) / 256;
    const int NB = (NN * 32 + 255) / 256;      // warp-per-node kernels
    const int PB = 296;                        // persistent GEMM: 2 CTA/SM

    k_detect<<<1, 1>>>((const unsigned*)EI);
    k_zero_deg<<<(NN + 255) / 256, 256>>>();
    k_convert<<<EB, 256>>>(EI);
    k_scan<<<1, 1024>>>();
    k_scatter<<<EB, 256>>>();

    k_gemm_mma<<<dim3(PB, 3), 256, GEMM_SMEM>>>(X, Wq, Wk, Wv, bq, bk, bv,
                                                qp, kp, vp, NN);
    k_scores_csr<<<NB, 256>>>(qp, kp);
    k_agg_csr<<<NB, 256>>>(vp, aggp);
    k_gemm_mma<<<dim3(PB, 1), 256, GEMM_SMEM>>>(aggp, Wo, Wo, Wo, bo, bo, bo,
                                                out, out, out, NN);
}

// round 15
// speedup vs baseline: 2.0730x; 1.2059x over previous
#include <cuda_runtime.h>
#include <cuda_bf16.h>

#define NN   50000
#define EE   600000
#define FEATD 128
#define NH   8
#define SCAN_BLK 512
#define NSB ((NN + SCAN_BLK - 1) / SCAN_BLK)   // 98

// ---------------- scratch (static device globals: allocation-guard safe) ---
__device__ float g_q[NN * FEATD];
__device__ float g_k[NN * FEATD];
__device__ float g_v[NN * FEATD];
__device__ float g_agg[NN * FEATD];
__device__ float g_ex[EE * NH];          // exp scores -> normalized weights
__device__ int   g_src[EE];
__device__ int   g_dst[EE];
__device__ int   g_is64;
// CSR (both directions)
__device__ int g_deg_s[NN], g_deg_d[NN];
__device__ int g_off_s[NN + 1], g_off_d[NN + 1];
__device__ int g_cur_s[NN], g_cur_d[NN];
__device__ int g_bsum_s[NSB], g_bsum_d[NSB];
__device__ int g_boff_s[NSB], g_boff_d[NSB];
__device__ int g_csr_s_dst[EE], g_csr_s_eid[EE];   // by-src: (dst, edge id)
__device__ int g_csr_d_src[EE], g_csr_d_eid[EE];   // by-dst: (src, edge id)

// ============================ PTX helpers (arch-agnostic only!) =============
__device__ __forceinline__ unsigned smem_u32(const void* p) {
    unsigned a;
    asm("{ .reg .u64 t; cvta.to.shared.u64 t, %1; cvt.u32.u64 %0, t; }"
        : "=r"(a) : "l"(p));
    return a;
}

#define LDSM_X4(r, addr) \
    asm volatile("ldmatrix.sync.aligned.m8n8.x4.shared.b16 {%0,%1,%2,%3}, [%4];" \
                 : "=r"((r)[0]), "=r"((r)[1]), "=r"((r)[2]), "=r"((r)[3])        \
                 : "r"(addr))

#define MMA_BF16(d, a, b0, b1)                                                  \
    asm volatile("mma.sync.aligned.m16n8k16.row.col.f32.bf16.bf16.f32 "         \
                 "{%0,%1,%2,%3}, {%4,%5,%6,%7}, {%8,%9}, {%0,%1,%2,%3};"        \
                 : "+f"((d)[0]), "+f"((d)[1]), "+f"((d)[2]), "+f"((d)[3])        \
                 : "r"((a)[0]), "r"((a)[1]), "r"((a)[2]), "r"((a)[3]),           \
                   "r"(b0), "r"(b1))

// =================== fused-split mma.sync GEMM (persistent) =================
// out = A @ W^T + b ; W selected by blockIdx.y, loaded ONCE per block; block
// grid-strides over 64-row A tiles. A fp32 split in-register to bf16 hi/lo:
// D = A1B1 + A1B2 + A2B1 (rel err ~2^-17). 8 warps as 2(M) x 4(N).
// Smem rows strided 272 B (17 x 16B banks -> ldmatrix conflict-free).
static constexpr int SM_X1   = 0;                    // 64 x 272
static constexpr int SM_X2   = 64 * 272;             // 17408
static constexpr int SM_W1   = 2 * 64 * 272;         // 34816, 128 x 272
static constexpr int SM_W2   = SM_W1 + 128 * 272;    // 69632
static constexpr int SM_BIAS = SM_W2 + 128 * 272;    // 104448
static constexpr int GEMM_SMEM = SM_BIAS + 512;      // 104960 B -> 2 CTA/SM

__device__ __forceinline__ void load_split_tile(char* sm, int offH, int offL,
                                                const float* __restrict__ g,
                                                int row0, int tile_rows, int nrows) {
    for (int c = threadIdx.x; c < tile_rows * 32; c += 256) {
        int r = c >> 5, c4 = c & 31;
        float4 v = make_float4(0.f, 0.f, 0.f, 0.f);
        int gr = row0 + r;
        if (gr < nrows) v = ((const float4*)(g + (size_t)gr * FEATD))[c4];
        __nv_bfloat162 h01 = __floats2bfloat162_rn(v.x, v.y);
        __nv_bfloat162 h23 = __floats2bfloat162_rn(v.z, v.w);
        float2 f01 = __bfloat1622float2(h01);
        float2 f23 = __bfloat1622float2(h23);
        __nv_bfloat162 l01 = __floats2bfloat162_rn(v.x - f01.x, v.y - f01.y);
        __nv_bfloat162 l23 = __floats2bfloat162_rn(v.z - f23.x, v.w - f23.y);
        unsigned base = r * 272 + c4 * 8;
        *(uint2*)(sm + offH + base) =
            make_uint2(*(unsigned*)&h01, *(unsigned*)&h23);
        *(uint2*)(sm + offL + base) =
            make_uint2(*(unsigned*)&l01, *(unsigned*)&l23);
    }
}

__global__ void __launch_bounds__(256, 2)
k_gemm_mma(const float* __restrict__ A,
           const float* __restrict__ W0, const float* __restrict__ W1,
           const float* __restrict__ W2,
           const float* __restrict__ b0, const float* __restrict__ b1,
           const float* __restrict__ b2,
           float* __restrict__ o0, float* __restrict__ o1,
           float* __restrict__ o2, int nrows) {
    extern __shared__ char sm[];
    const int tid = threadIdx.x, wid = tid >> 5, lane = tid & 31;
    const int j = blockIdx.y;

    const float* W  = (j == 0) ? W0 : (j == 1) ? W1 : W2;
    const float* bp = (j == 0) ? b0 : (j == 1) ? b1 : b2;
    float*      out = (j == 0) ? o0 : (j == 1) ? o1 : o2;

    if (tid < FEATD) ((float*)(sm + SM_BIAS))[tid] = bp[tid];
    load_split_tile(sm, SM_W1, SM_W2, W, 0, 128, 128);   // once per block

    const unsigned sbase = smem_u32(sm);
    const int warp_m = wid & 1, warp_n = wid >> 1;

    const int a_r    = lane & 15;
    const int a_koff = (lane >> 4) << 4;
    const unsigned a1_base = sbase + SM_X1 + (warp_m * 32 + a_r) * 272 + a_koff;
    const unsigned a2_base = sbase + SM_X2 + (warp_m * 32 + a_r) * 272 + a_koff;

    const int b_r    = (lane & 7) | ((lane & 16) >> 1);
    const int b_koff = (lane & 8) << 1;
    const unsigned b1_base = sbase + SM_W1 + (warp_n * 32 + b_r) * 272 + b_koff;
    const unsigned b2_base = sbase + SM_W2 + (warp_n * 32 + b_r) * 272 + b_koff;

    const int g = lane >> 2, t = lane & 3;
    const float* bs = (const float*)(sm + SM_BIAS);
    const int ntiles = (nrows + 63) >> 6;

    for (int tile = blockIdx.x; tile < ntiles; tile += gridDim.x) {
        const int row0 = tile * 64;
        __syncthreads();   // W ready (1st iter) / prev tile's reads done
        load_split_tile(sm, SM_X1, SM_X2, A, row0, 64, nrows);
        __syncthreads();

        float acc[2][4][4];
#pragma unroll
        for (int i = 0; i < 2; i++)
#pragma unroll
            for (int f = 0; f < 4; f++)
#pragma unroll
                for (int c = 0; c < 4; c++) acc[i][f][c] = 0.f;

#pragma unroll
        for (int kk = 0; kk < 8; kk++) {
            const unsigned ko = kk * 32;
            unsigned a1[2][4], a2[2][4];
            LDSM_X4(a1[0], a1_base + ko);
            LDSM_X4(a1[1], a1_base + 16 * 272 + ko);
            LDSM_X4(a2[0], a2_base + ko);
            LDSM_X4(a2[1], a2_base + 16 * 272 + ko);

            unsigned w1[2][4], w2[2][4];
            LDSM_X4(w1[0], b1_base + ko);
            LDSM_X4(w1[1], b1_base + 16 * 272 + ko);
            LDSM_X4(w2[0], b2_base + ko);
            LDSM_X4(w2[1], b2_base + 16 * 272 + ko);

            // term-major: same acc reused only every 8 MMAs (no RAW stall)
#pragma unroll
            for (int fm = 0; fm < 2; fm++)
#pragma unroll
                for (int nb = 0; nb < 2; nb++) {
                    MMA_BF16(acc[fm][2 * nb + 0], a1[fm], w1[nb][0], w1[nb][1]);
                    MMA_BF16(acc[fm][2 * nb + 1], a1[fm], w1[nb][2], w1[nb][3]);
                }
#pragma unroll
            for (int fm = 0; fm < 2; fm++)
#pragma unroll
                for (int nb = 0; nb < 2; nb++) {
                    MMA_BF16(acc[fm][2 * nb + 0], a1[fm], w2[nb][0], w2[nb][1]);
                    MMA_BF16(acc[fm][2 * nb + 1], a1[fm], w2[nb][2], w2[nb][3]);
                }
#pragma unroll
            for (int fm = 0; fm < 2; fm++)
#pragma unroll
                for (int nb = 0; nb < 2; nb++) {
                    MMA_BF16(acc[fm][2 * nb + 0], a2[fm], w1[nb][0], w1[nb][1]);
                    MMA_BF16(acc[fm][2 * nb + 1], a2[fm], w1[nb][2], w1[nb][3]);
                }
        }

#pragma unroll
        for (int fm = 0; fm < 2; fm++) {
            const int r0 = row0 + warp_m * 32 + fm * 16 + g;
#pragma unroll
            for (int fn = 0; fn < 4; fn++) {
                const int col = warp_n * 32 + fn * 8 + 2 * t;
                if (r0 < nrows) {
                    float2 o = make_float2(acc[fm][fn][0] + bs[col],
                                           acc[fm][fn][1] + bs[col + 1]);
                    *(float2*)(out + (size_t)r0 * FEATD + col) = o;
                }
                if (r0 + 8 < nrows) {
                    float2 o = make_float2(acc[fm][fn][2] + bs[col],
                                           acc[fm][fn][3] + bs[col + 1]);
                    *(float2*)(out + (size_t)(r0 + 8) * FEATD + col) = o;
                }
            }
        }
    }
}

// ---------------- edge-index dtype detection --------------------------------
__global__ void k_detect(const unsigned* __restrict__ ei) {
    unsigned acc = 0;
#pragma unroll
    for (int i = 0; i < 16; i++) acc |= ei[2 * i + 1];
    g_is64 = (acc == 0) ? 1 : 0;
}

__global__ void k_zero_deg() {
    int i = blockIdx.x * blockDim.x + threadIdx.x;
    if (i < NN) { g_deg_s[i] = 0; g_deg_d[i] = 0; }
}

// convert + degree histogram
__global__ void k_convert(const void* __restrict__ ei) {
    int e = blockIdx.x * blockDim.x + threadIdx.x;
    if (e >= EE) return;
    int s, d;
    if (g_is64) {
        const long long* p = (const long long*)ei;
        s = (int)p[e]; d = (int)p[EE + e];
    } else {
        const int* p = (const int*)ei;
        s = p[e]; d = p[EE + e];
    }
    g_src[e] = s; g_dst[e] = d;
    atomicAdd(&g_deg_s[s], 1);
    atomicAdd(&g_deg_d[d], 1);
}

// ---------------- 3-phase multi-block exclusive scan ------------------------
// phase 1: per-block local exclusive scan (both arrays), block totals out
__global__ void __launch_bounds__(SCAN_BLK) k_scan1() {
    __shared__ int ws[16], wd[16];
    const int t = threadIdx.x, lane = t & 31, w = t >> 5;
    const int i = blockIdx.x * SCAN_BLK + t;
    int vs = (i < NN) ? g_deg_s[i] : 0;
    int vd = (i < NN) ? g_deg_d[i] : 0;
    int ss = vs, sd = vd;
#pragma unroll
    for (int o = 1; o < 32; o <<= 1) {
        int ts = __shfl_up_sync(0xffffffffu, ss, o);
        int td = __shfl_up_sync(0xffffffffu, sd, o);
        if (lane >= o) { ss += ts; sd += td; }
    }
    if (lane == 31) { ws[w] = ss; wd[w] = sd; }
    __syncthreads();
    if (w == 0 && lane < 16) {
        int xs = ws[lane], xd = wd[lane];
        int is = xs, id = xd;
#pragma unroll
        for (int o = 1; o < 16; o <<= 1) {
            int ts = __shfl_up_sync(0xffffu, is, o);
            int td = __shfl_up_sync(0xffffu, id, o);
            if (lane >= o) { is += ts; id += td; }
        }
        ws[lane] = is - xs;   // exclusive warp offsets
        wd[lane] = id - xd;
    }
    __syncthreads();
    const int es = ss - vs + ws[w];
    const int ed = sd - vd + wd[w];
    if (i < NN) { g_off_s[i] = es; g_off_d[i] = ed; }
    if (t == SCAN_BLK - 1) {
        g_bsum_s[blockIdx.x] = es + vs;
        g_bsum_d[blockIdx.x] = ed + vd;
    }
}

// phase 2: scan the NSB block totals (single tiny block)
__global__ void __launch_bounds__(128) k_scan2() {
    __shared__ int ws[4], wd[4];
    const int t = threadIdx.x, lane = t & 31, w = t >> 5;
    int vs = (t < NSB) ? g_bsum_s[t] : 0;
    int vd = (t < NSB) ? g_bsum_d[t] : 0;
    int ss = vs, sd = vd;
#pragma unroll
    for (int o = 1; o < 32; o <<= 1) {
        int ts = __shfl_up_sync(0xffffffffu, ss, o);
        int td = __shfl_up_sync(0xffffffffu, sd, o);
        if (lane >= o) { ss += ts; sd += td; }
    }
    if (lane == 31) { ws[w] = ss; wd[w] = sd; }
    __syncthreads();
    if (w == 0 && lane < 4) {
        int xs = ws[lane], xd = wd[lane];
        int is = xs, id = xd;
#pragma unroll
        for (int o = 1; o < 4; o <<= 1) {
            int ts = __shfl_up_sync(0xfu, is, o);
            int td = __shfl_up_sync(0xfu, id, o);
            if (lane >= o) { is += ts; id += td; }
        }
        ws[lane] = is - xs;
        wd[lane] = id - xd;
    }
    __syncthreads();
    if (t < NSB) {
        g_boff_s[t] = ss - vs + ws[w];
        g_boff_d[t] = sd - vd + wd[w];
    }
}

// phase 3: add block offsets, materialize off/cur; totals are statically EE
__global__ void __launch_bounds__(SCAN_BLK) k_scan3() {
    const int i = blockIdx.x * SCAN_BLK + threadIdx.x;
    if (i < NN) {
        int es = g_off_s[i] + g_boff_s[blockIdx.x];
        int ed = g_off_d[i] + g_boff_d[blockIdx.x];
        g_off_s[i] = es; g_cur_s[i] = es;
        g_off_d[i] = ed; g_cur_d[i] = ed;
    }
    if (i == 0) { g_off_s[NN] = EE; g_off_d[NN] = EE; }
}

__global__ void k_scatter() {
    int e = blockIdx.x * blockDim.x + threadIdx.x;
    if (e >= EE) return;
    int s = g_src[e], d = g_dst[e];
    int ps = atomicAdd(&g_cur_s[s], 1);
    g_csr_s_dst[ps] = d; g_csr_s_eid[ps] = e;
    int pd = atomicAdd(&g_cur_d[d], 1);
    g_csr_d_src[pd] = s; g_csr_d_eid[pd] = e;
}

// ------- scores (warp per src node): softmax over outgoing edges, no atomics
__global__ void k_scores_csr(const float* __restrict__ q,
                             const float* __restrict__ k) {
    int n = (blockIdx.x * blockDim.x + threadIdx.x) >> 5;
    if (n >= NN) return;
    int lane = threadIdx.x & 31;
    float4 qv = ((const float4*)q)[n * 32 + lane];   // q held in registers
    int beg = g_off_s[n], end = g_off_s[n + 1];

    float ssum = 0.f;   // per-head sum lives in lanes with (lane&3)==0
    for (int j = beg; j < end; j++) {
        int d = g_csr_s_dst[j];
        int e = g_csr_s_eid[j];
        float4 kv = ((const float4*)k)[d * 32 + lane];
        float p = qv.x * kv.x + qv.y * kv.y + qv.z * kv.z + qv.w * kv.w;
        p += __shfl_xor_sync(0xffffffffu, p, 1);
        p += __shfl_xor_sync(0xffffffffu, p, 2);
        if ((lane & 3) == 0) {
            float exv = __expf(p * 0.25f);
            g_ex[e * NH + (lane >> 2)] = exv;
            ssum += exv;
        }
    }
    // normalize in place: g_ex becomes final weights
    if ((lane & 3) == 0 && end > beg) {
        float inv = 1.f / ssum;
        int h = lane >> 2;
        for (int j = beg; j < end; j++) {
            int e = g_csr_s_eid[j];
            g_ex[e * NH + h] *= inv;
        }
    }
}

// ------- aggregation (warp per dst node): register accumulate, single store
__global__ void k_agg_csr(const float* __restrict__ v, float* __restrict__ agg) {
    int n = (blockIdx.x * blockDim.x + threadIdx.x) >> 5;
    if (n >= NN) return;
    int lane = threadIdx.x & 31;
    int h = lane >> 2;
    int beg = g_off_d[n], end = g_off_d[n + 1];

    float4 acc = make_float4(0.f, 0.f, 0.f, 0.f);
    for (int j = beg; j < end; j++) {
        int s = g_csr_d_src[j];
        int e = g_csr_d_eid[j];
        float w = g_ex[e * NH + h];
        float4 vv = ((const float4*)v)[s * 32 + lane];
        acc.x += w * vv.x; acc.y += w * vv.y;
        acc.z += w * vv.z; acc.w += w * vv.w;
    }
    ((float4*)agg)[n * 32 + lane] = acc;
}

// ---------------- launch -----------------------------------------------------
extern "C" void kernel_launch(void* const* d_in, const int* in_sizes, int n_in,
                              void* d_out, int out_size) {
    const float* X  = (const float*)d_in[0];
    const void*  EI = d_in[1];
    const float* Wq = (const float*)d_in[2];
    const float* bq = (const float*)d_in[3];
    const float* Wk = (const float*)d_in[4];
    const float* bk = (const float*)d_in[5];
    const float* Wv = (const float*)d_in[6];
    const float* bv = (const float*)d_in[7];
    const float* Wo = (const float*)d_in[8];
    const float* bo = (const float*)d_in[9];
    float* out = (float*)d_out;

    float *qp, *kp, *vp, *aggp;
    cudaGetSymbolAddress((void**)&qp,   g_q);
    cudaGetSymbolAddress((void**)&kp,   g_k);
    cudaGetSymbolAddress((void**)&vp,   g_v);
    cudaGetSymbolAddress((void**)&aggp, g_agg);

    cudaFuncSetAttribute(k_gemm_mma, cudaFuncAttributeMaxDynamicSharedMemorySize,
                         GEMM_SMEM);

    const int EB = (EE + 255) / 256;
    const int NB = (NN * 32 + 255) / 256;      // warp-per-node kernels
    const int PB = 296;                        // persistent GEMM: 2 CTA/SM

    k_detect<<<1, 1>>>((const unsigned*)EI);
    k_zero_deg<<<(NN + 255) / 256, 256>>>();
    k_convert<<<EB, 256>>>(EI);
    k_scan1<<<NSB, SCAN_BLK>>>();
    k_scan2<<<1, 128>>>();
    k_scan3<<<NSB, SCAN_BLK>>>();
    k_scatter<<<EB, 256>>>();

    k_gemm_mma<<<dim3(PB, 3), 256, GEMM_SMEM>>>(X, Wq, Wk, Wv, bq, bk, bv,
                                                qp, kp, vp, NN);
    k_scores_csr<<<NB, 256>>>(qp, kp);
    k_agg_csr<<<NB, 256>>>(vp, aggp);
    k_gemm_mma<<<dim3(PB, 1), 256, GEMM_SMEM>>>(aggp, Wo, Wo, Wo, bo, bo, bo,
                                                out, out, out, NN);
}

// round 16
// speedup vs baseline: 2.1307x; 1.0278x over previous
#include <cuda_runtime.h>
#include <cuda_bf16.h>

#define NN   50000
#define EE   600000
#define FEATD 128
#define NH   8
#define SCAN_BLK 512
#define NSB ((NN + SCAN_BLK - 1) / SCAN_BLK)   // 98

// ---------------- scratch (static device globals: allocation-guard safe) ---
__device__ float g_q[NN * FEATD];
__device__ float g_k[NN * FEATD];
__device__ float g_v[NN * FEATD];
__device__ float g_agg[NN * FEATD];
__device__ float g_ex[EE * NH];          // exp scores -> normalized weights
__device__ int   g_src[EE];
__device__ int   g_dst[EE];
__device__ int   g_is64;
// CSR (both directions)
__device__ int g_deg_s[NN], g_deg_d[NN];
__device__ int g_off_s[NN + 1], g_off_d[NN + 1];
__device__ int g_cur_s[NN], g_cur_d[NN];
__device__ int g_bsum_s[NSB], g_bsum_d[NSB];
__device__ int g_boff_s[NSB], g_boff_d[NSB];
__device__ int g_csr_s_dst[EE], g_csr_s_eid[EE];   // by-src: (dst, edge id)
__device__ int g_csr_d_src[EE], g_csr_d_eid[EE];   // by-dst: (src, edge id)

// ============================ PTX helpers (arch-agnostic only!) =============
__device__ __forceinline__ unsigned smem_u32(const void* p) {
    unsigned a;
    asm("{ .reg .u64 t; cvta.to.shared.u64 t, %1; cvt.u32.u64 %0, t; }"
        : "=r"(a) : "l"(p));
    return a;
}

#define LDSM_X4(r, addr) \
    asm volatile("ldmatrix.sync.aligned.m8n8.x4.shared.b16 {%0,%1,%2,%3}, [%4];" \
                 : "=r"((r)[0]), "=r"((r)[1]), "=r"((r)[2]), "=r"((r)[3])        \
                 : "r"(addr))

#define MMA_BF16(d, a, b0, b1)                                                  \
    asm volatile("mma.sync.aligned.m16n8k16.row.col.f32.bf16.bf16.f32 "         \
                 "{%0,%1,%2,%3}, {%4,%5,%6,%7}, {%8,%9}, {%0,%1,%2,%3};"        \
                 : "+f"((d)[0]), "+f"((d)[1]), "+f"((d)[2]), "+f"((d)[3])        \
                 : "r"((a)[0]), "r"((a)[1]), "r"((a)[2]), "r"((a)[3]),           \
                   "r"(b0), "r"(b1))

// =================== fused-split mma.sync GEMM (persistent, pipelined) ======
// out = A @ W^T + b ; W selected by blockIdx.y, loaded ONCE per block; block
// grid-strides over 64-row A tiles with REGISTER PREFETCH of the next tile
// (LDG issued before the MMA phase; compute hides DRAM latency).
// A fp32 split in-register to bf16 hi/lo: D = A1B1 + A1B2 + A2B1 (~2^-17).
// 8 warps as 2(M) x 4(N). Smem rows strided 272 B (conflict-free ldmatrix).
static constexpr int SM_X1   = 0;                    // 64 x 272
static constexpr int SM_X2   = 64 * 272;             // 17408
static constexpr int SM_W1   = 2 * 64 * 272;         // 34816, 128 x 272
static constexpr int SM_W2   = SM_W1 + 128 * 272;    // 69632
static constexpr int SM_BIAS = SM_W2 + 128 * 272;    // 104448
static constexpr int GEMM_SMEM = SM_BIAS + 512;      // 104960 B -> 2 CTA/SM

__device__ __forceinline__ void load_split_tile(char* sm, int offH, int offL,
                                                const float* __restrict__ g,
                                                int row0, int tile_rows, int nrows) {
    for (int c = threadIdx.x; c < tile_rows * 32; c += 256) {
        int r = c >> 5, c4 = c & 31;
        float4 v = make_float4(0.f, 0.f, 0.f, 0.f);
        int gr = row0 + r;
        if (gr < nrows) v = ((const float4*)(g + (size_t)gr * FEATD))[c4];
        __nv_bfloat162 h01 = __floats2bfloat162_rn(v.x, v.y);
        __nv_bfloat162 h23 = __floats2bfloat162_rn(v.z, v.w);
        float2 f01 = __bfloat1622float2(h01);
        float2 f23 = __bfloat1622float2(h23);
        __nv_bfloat162 l01 = __floats2bfloat162_rn(v.x - f01.x, v.y - f01.y);
        __nv_bfloat162 l23 = __floats2bfloat162_rn(v.z - f23.x, v.w - f23.y);
        unsigned base = r * 272 + c4 * 8;
        *(uint2*)(sm + offH + base) =
            make_uint2(*(unsigned*)&h01, *(unsigned*)&h23);
        *(uint2*)(sm + offL + base) =
            make_uint2(*(unsigned*)&l01, *(unsigned*)&l23);
    }
}

// X tile in registers: 8 float4 per thread (64 rows x 32 float4 / 256 thr)
__device__ __forceinline__ void ldg_xtile(float4 (&f)[8],
                                          const float* __restrict__ A,
                                          int row0, int nrows) {
#pragma unroll
    for (int i = 0; i < 8; i++) {
        int c = threadIdx.x + i * 256;
        int r = c >> 5, c4 = c & 31;
        int gr = row0 + r;
        f[i] = (gr < nrows) ? ((const float4*)(A + (size_t)gr * FEATD))[c4]
                            : make_float4(0.f, 0.f, 0.f, 0.f);
    }
}

__device__ __forceinline__ void sts_split_xtile(char* sm, const float4 (&f)[8]) {
#pragma unroll
    for (int i = 0; i < 8; i++) {
        int c = threadIdx.x + i * 256;
        int r = c >> 5, c4 = c & 31;
        float4 v = f[i];
        __nv_bfloat162 h01 = __floats2bfloat162_rn(v.x, v.y);
        __nv_bfloat162 h23 = __floats2bfloat162_rn(v.z, v.w);
        float2 f01 = __bfloat1622float2(h01);
        float2 f23 = __bfloat1622float2(h23);
        __nv_bfloat162 l01 = __floats2bfloat162_rn(v.x - f01.x, v.y - f01.y);
        __nv_bfloat162 l23 = __floats2bfloat162_rn(v.z - f23.x, v.w - f23.y);
        unsigned base = r * 272 + c4 * 8;
        *(uint2*)(sm + SM_X1 + base) =
            make_uint2(*(unsigned*)&h01, *(unsigned*)&h23);
        *(uint2*)(sm + SM_X2 + base) =
            make_uint2(*(unsigned*)&l01, *(unsigned*)&l23);
    }
}

__global__ void __launch_bounds__(256, 2)
k_gemm_mma(const float* __restrict__ A,
           const float* __restrict__ W0, const float* __restrict__ W1,
           const float* __restrict__ W2,
           const float* __restrict__ b0, const float* __restrict__ b1,
           const float* __restrict__ b2,
           float* __restrict__ o0, float* __restrict__ o1,
           float* __restrict__ o2, int nrows) {
    extern __shared__ char sm[];
    const int tid = threadIdx.x, wid = tid >> 5, lane = tid & 31;
    const int j = blockIdx.y;

    const float* W  = (j == 0) ? W0 : (j == 1) ? W1 : W2;
    const float* bp = (j == 0) ? b0 : (j == 1) ? b1 : b2;
    float*      out = (j == 0) ? o0 : (j == 1) ? o1 : o2;

    if (tid < FEATD) ((float*)(sm + SM_BIAS))[tid] = bp[tid];
    load_split_tile(sm, SM_W1, SM_W2, W, 0, 128, 128);   // once per block

    const unsigned sbase = smem_u32(sm);
    const int warp_m = wid & 1, warp_n = wid >> 1;

    const int a_r    = lane & 15;
    const int a_koff = (lane >> 4) << 4;
    const unsigned a1_base = sbase + SM_X1 + (warp_m * 32 + a_r) * 272 + a_koff;
    const unsigned a2_base = sbase + SM_X2 + (warp_m * 32 + a_r) * 272 + a_koff;

    const int b_r    = (lane & 7) | ((lane & 16) >> 1);
    const int b_koff = (lane & 8) << 1;
    const unsigned b1_base = sbase + SM_W1 + (warp_n * 32 + b_r) * 272 + b_koff;
    const unsigned b2_base = sbase + SM_W2 + (warp_n * 32 + b_r) * 272 + b_koff;

    const int g = lane >> 2, t = lane & 3;
    const float* bs = (const float*)(sm + SM_BIAS);
    const int ntiles = (nrows + 63) >> 6;

    float4 xf[8];
    int tile = blockIdx.x;
    if (tile < ntiles) ldg_xtile(xf, A, tile * 64, nrows);

    for (; tile < ntiles; tile += gridDim.x) {
        const int row0 = tile * 64;
        __syncthreads();   // W ready (1st iter) / prev tile's smem reads done
        sts_split_xtile(sm, xf);
        __syncthreads();

        // prefetch NEXT tile while this tile's MMAs run
        const int nxt = tile + gridDim.x;
        if (nxt < ntiles) ldg_xtile(xf, A, nxt * 64, nrows);

        float acc[2][4][4];
#pragma unroll
        for (int i = 0; i < 2; i++)
#pragma unroll
            for (int f = 0; f < 4; f++)
#pragma unroll
                for (int c = 0; c < 4; c++) acc[i][f][c] = 0.f;

#pragma unroll
        for (int kk = 0; kk < 8; kk++) {
            const unsigned ko = kk * 32;
            unsigned a1[2][4], a2[2][4];
            LDSM_X4(a1[0], a1_base + ko);
            LDSM_X4(a1[1], a1_base + 16 * 272 + ko);
            LDSM_X4(a2[0], a2_base + ko);
            LDSM_X4(a2[1], a2_base + 16 * 272 + ko);

            unsigned w1[2][4], w2[2][4];
            LDSM_X4(w1[0], b1_base + ko);
            LDSM_X4(w1[1], b1_base + 16 * 272 + ko);
            LDSM_X4(w2[0], b2_base + ko);
            LDSM_X4(w2[1], b2_base + 16 * 272 + ko);

            // term-major: same acc reused only every 8 MMAs (no RAW stall)
#pragma unroll
            for (int fm = 0; fm < 2; fm++)
#pragma unroll
                for (int nb = 0; nb < 2; nb++) {
                    MMA_BF16(acc[fm][2 * nb + 0], a1[fm], w1[nb][0], w1[nb][1]);
                    MMA_BF16(acc[fm][2 * nb + 1], a1[fm], w1[nb][2], w1[nb][3]);
                }
#pragma unroll
            for (int fm = 0; fm < 2; fm++)
#pragma unroll
                for (int nb = 0; nb < 2; nb++) {
                    MMA_BF16(acc[fm][2 * nb + 0], a1[fm], w2[nb][0], w2[nb][1]);
                    MMA_BF16(acc[fm][2 * nb + 1], a1[fm], w2[nb][2], w2[nb][3]);
                }
#pragma unroll
            for (int fm = 0; fm < 2; fm++)
#pragma unroll
                for (int nb = 0; nb < 2; nb++) {
                    MMA_BF16(acc[fm][2 * nb + 0], a2[fm], w1[nb][0], w1[nb][1]);
                    MMA_BF16(acc[fm][2 * nb + 1], a2[fm], w1[nb][2], w1[nb][3]);
                }
        }

#pragma unroll
        for (int fm = 0; fm < 2; fm++) {
            const int r0 = row0 + warp_m * 32 + fm * 16 + g;
#pragma unroll
            for (int fn = 0; fn < 4; fn++) {
                const int col = warp_n * 32 + fn * 8 + 2 * t;
                if (r0 < nrows) {
                    float2 o = make_float2(acc[fm][fn][0] + bs[col],
                                           acc[fm][fn][1] + bs[col + 1]);
                    *(float2*)(out + (size_t)r0 * FEATD + col) = o;
                }
                if (r0 + 8 < nrows) {
                    float2 o = make_float2(acc[fm][fn][2] + bs[col],
                                           acc[fm][fn][3] + bs[col + 1]);
                    *(float2*)(out + (size_t)(r0 + 8) * FEATD + col) = o;
                }
            }
        }
    }
}

// ---------------- edge-index dtype detection --------------------------------
__global__ void k_detect(const unsigned* __restrict__ ei) {
    unsigned acc = 0;
#pragma unroll
    for (int i = 0; i < 16; i++) acc |= ei[2 * i + 1];
    g_is64 = (acc == 0) ? 1 : 0;
}

__global__ void k_zero_deg() {
    int i = blockIdx.x * blockDim.x + threadIdx.x;
    if (i < NN) { g_deg_s[i] = 0; g_deg_d[i] = 0; }
}

// convert + degree histogram
__global__ void k_convert(const void* __restrict__ ei) {
    int e = blockIdx.x * blockDim.x + threadIdx.x;
    if (e >= EE) return;
    int s, d;
    if (g_is64) {
        const long long* p = (const long long*)ei;
        s = (int)p[e]; d = (int)p[EE + e];
    } else {
        const int* p = (const int*)ei;
        s = p[e]; d = p[EE + e];
    }
    g_src[e] = s; g_dst[e] = d;
    atomicAdd(&g_deg_s[s], 1);
    atomicAdd(&g_deg_d[d], 1);
}

// ---------------- 3-phase multi-block exclusive scan ------------------------
__global__ void __launch_bounds__(SCAN_BLK) k_scan1() {
    __shared__ int ws[16], wd[16];
    const int t = threadIdx.x, lane = t & 31, w = t >> 5;
    const int i = blockIdx.x * SCAN_BLK + t;
    int vs = (i < NN) ? g_deg_s[i] : 0;
    int vd = (i < NN) ? g_deg_d[i] : 0;
    int ss = vs, sd = vd;
#pragma unroll
    for (int o = 1; o < 32; o <<= 1) {
        int ts = __shfl_up_sync(0xffffffffu, ss, o);
        int td = __shfl_up_sync(0xffffffffu, sd, o);
        if (lane >= o) { ss += ts; sd += td; }
    }
    if (lane == 31) { ws[w] = ss; wd[w] = sd; }
    __syncthreads();
    if (w == 0 && lane < 16) {
        int xs = ws[lane], xd = wd[lane];
        int is = xs, id = xd;
#pragma unroll
        for (int o = 1; o < 16; o <<= 1) {
            int ts = __shfl_up_sync(0xffffu, is, o);
            int td = __shfl_up_sync(0xffffu, id, o);
            if (lane >= o) { is += ts; id += td; }
        }
        ws[lane] = is - xs;   // exclusive warp offsets
        wd[lane] = id - xd;
    }
    __syncthreads();
    const int es = ss - vs + ws[w];
    const int ed = sd - vd + wd[w];
    if (i < NN) { g_off_s[i] = es; g_off_d[i] = ed; }
    if (t == SCAN_BLK - 1) {
        g_bsum_s[blockIdx.x] = es + vs;
        g_bsum_d[blockIdx.x] = ed + vd;
    }
}

__global__ void __launch_bounds__(128) k_scan2() {
    __shared__ int ws[4], wd[4];
    const int t = threadIdx.x, lane = t & 31, w = t >> 5;
    int vs = (t < NSB) ? g_bsum_s[t] : 0;
    int vd = (t < NSB) ? g_bsum_d[t] : 0;
    int ss = vs, sd = vd;
#pragma unroll
    for (int o = 1; o < 32; o <<= 1) {
        int ts = __shfl_up_sync(0xffffffffu, ss, o);
        int td = __shfl_up_sync(0xffffffffu, sd, o);
        if (lane >= o) { ss += ts; sd += td; }
    }
    if (lane == 31) { ws[w] = ss; wd[w] = sd; }
    __syncthreads();
    if (w == 0 && lane < 4) {
        int xs = ws[lane], xd = wd[lane];
        int is = xs, id = xd;
#pragma unroll
        for (int o = 1; o < 4; o <<= 1) {
            int ts = __shfl_up_sync(0xfu, is, o);
            int td = __shfl_up_sync(0xfu, id, o);
            if (lane >= o) { is += ts; id += td; }
        }
        ws[lane] = is - xs;
        wd[lane] = id - xd;
    }
    __syncthreads();
    if (t < NSB) {
        g_boff_s[t] = ss - vs + ws[w];
        g_boff_d[t] = sd - vd + wd[w];
    }
}

__global__ void __launch_bounds__(SCAN_BLK) k_scan3() {
    const int i = blockIdx.x * SCAN_BLK + threadIdx.x;
    if (i < NN) {
        int es = g_off_s[i] + g_boff_s[blockIdx.x];
        int ed = g_off_d[i] + g_boff_d[blockIdx.x];
        g_off_s[i] = es; g_cur_s[i] = es;
        g_off_d[i] = ed; g_cur_d[i] = ed;
    }
    if (i == 0) { g_off_s[NN] = EE; g_off_d[NN] = EE; }
}

__global__ void k_scatter() {
    int e = blockIdx.x * blockDim.x + threadIdx.x;
    if (e >= EE) return;
    int s = g_src[e], d = g_dst[e];
    int ps = atomicAdd(&g_cur_s[s], 1);
    g_csr_s_dst[ps] = d; g_csr_s_eid[ps] = e;
    int pd = atomicAdd(&g_cur_d[d], 1);
    g_csr_d_src[pd] = s; g_csr_d_eid[pd] = e;
}

// ------- scores (warp per src node): softmax over outgoing edges, no atomics
__global__ void k_scores_csr(const float* __restrict__ q,
                             const float* __restrict__ k) {
    int n = (blockIdx.x * blockDim.x + threadIdx.x) >> 5;
    if (n >= NN) return;
    int lane = threadIdx.x & 31;
    float4 qv = ((const float4*)q)[n * 32 + lane];   // q held in registers
    int beg = g_off_s[n], end = g_off_s[n + 1];

    float ssum = 0.f;   // per-head sum lives in lanes with (lane&3)==0
    for (int j = beg; j < end; j++) {
        int d = g_csr_s_dst[j];
        int e = g_csr_s_eid[j];
        float4 kv = ((const float4*)k)[d * 32 + lane];
        float p = qv.x * kv.x + qv.y * kv.y + qv.z * kv.z + qv.w * kv.w;
        p += __shfl_xor_sync(0xffffffffu, p, 1);
        p += __shfl_xor_sync(0xffffffffu, p, 2);
        if ((lane & 3) == 0) {
            float exv = __expf(p * 0.25f);
            g_ex[e * NH + (lane >> 2)] = exv;
            ssum += exv;
        }
    }
    // normalize in place: g_ex becomes final weights
    if ((lane & 3) == 0 && end > beg) {
        float inv = 1.f / ssum;
        int h = lane >> 2;
        for (int j = beg; j < end; j++) {
            int e = g_csr_s_eid[j];
            g_ex[e * NH + h] *= inv;
        }
    }
}

// ------- aggregation (warp per dst node): register accumulate, single store
__global__ void k_agg_csr(const float* __restrict__ v, float* __restrict__ agg) {
    int n = (blockIdx.x * blockDim.x + threadIdx.x) >> 5;
    if (n >= NN) return;
    int lane = threadIdx.x & 31;
    int h = lane >> 2;
    int beg = g_off_d[n], end = g_off_d[n + 1];

    float4 acc = make_float4(0.f, 0.f, 0.f, 0.f);
    for (int j = beg; j < end; j++) {
        int s = g_csr_d_src[j];
        int e = g_csr_d_eid[j];
        float w = g_ex[e * NH + h];
        float4 vv = ((const float4*)v)[s * 32 + lane];
        acc.x += w * vv.x; acc.y += w * vv.y;
        acc.z += w * vv.z; acc.w += w * vv.w;
    }
    ((float4*)agg)[n * 32 + lane] = acc;
}

// ---------------- launch -----------------------------------------------------
extern "C" void kernel_launch(void* const* d_in, const int* in_sizes, int n_in,
                              void* d_out, int out_size) {
    const float* X  = (const float*)d_in[0];
    const void*  EI = d_in[1];
    const float* Wq = (const float*)d_in[2];
    const float* bq = (const float*)d_in[3];
    const float* Wk = (const float*)d_in[4];
    const float* bk = (const float*)d_in[5];
    const float* Wv = (const float*)d_in[6];
    const float* bv = (const float*)d_in[7];
    const float* Wo = (const float*)d_in[8];
    const float* bo = (const float*)d_in[9];
    float* out = (float*)d_out;

    float *qp, *kp, *vp, *aggp;
    cudaGetSymbolAddress((void**)&qp,   g_q);
    cudaGetSymbolAddress((void**)&kp,   g_k);
    cudaGetSymbolAddress((void**)&vp,   g_v);
    cudaGetSymbolAddress((void**)&aggp, g_agg);

    cudaFuncSetAttribute(k_gemm_mma, cudaFuncAttributeMaxDynamicSharedMemorySize,
                         GEMM_SMEM);

    const int EB = (EE + 255) / 256;
    const int NB = (NN * 32 + 255) / 256;      // warp-per-node kernels
    const int PB = 296;                        // persistent GEMM: 2 CTA/SM

    k_detect<<<1, 1>>>((const unsigned*)EI);
    k_zero_deg<<<(NN + 255) / 256, 256>>>();
    k_convert<<<EB, 256>>>(EI);
    k_scan1<<<NSB, SCAN_BLK>>>();
    k_scan2<<<1, 128>>>();
    k_scan3<<<NSB, SCAN_BLK>>>();
    k_scatter<<<EB, 256>>>();

    k_gemm_mma<<<dim3(PB, 3), 256, GEMM_SMEM>>>(X, Wq, Wk, Wv, bq, bk, bv,
                                                qp, kp, vp, NN);
    k_scores_csr<<<NB, 256>>>(qp, kp);
    k_agg_csr<<<NB, 256>>>(vp, aggp);
    k_gemm_mma<<<dim3(PB, 1), 256, GEMM_SMEM>>>(aggp, Wo, Wo, Wo, bo, bo, bo,
                                                out, out, out, NN);
}